// round 3
// baseline (speedup 1.0000x reference)
#include <cuda_runtime.h>
#include <math.h>

#define D   128
#define D2  256
#define TM  32
#define NMAX 50000
#define NB_MEAN 200

// ---- scratch (device globals: allocation-free) ----
__device__ float g_h1[NMAX * D];     // h after step 1
__device__ float g_agg[NMAX * D];    // per-step aggregation
__device__ float g_part[NB_MEAN * D];
__device__ float g_repr[D];

// ---------------- helpers ----------------
__global__ void zero_agg_kernel(int total) {
    for (int i = blockIdx.x * blockDim.x + threadIdx.x; i < total;
         i += gridDim.x * blockDim.x)
        g_agg[i] = 0.f;
}

// partial column sums of x over node rows
__global__ void mean1_kernel(const float* __restrict__ x, int n) {
    int b = blockIdx.x, j = threadIdx.x;
    int per = (n + NB_MEAN - 1) / NB_MEAN;
    int r0 = b * per;
    int r1 = r0 + per; if (r1 > n) r1 = n;
    float s = 0.f;
    for (int r = r0; r < r1; r++) s += x[(size_t)r * D + j];
    g_part[b * D + j] = s;
}

// finish mean, compute global_repr = relu(mean @ glbW + glbB)
__global__ void repr_kernel(const float* __restrict__ glbW,
                            const float* __restrict__ glbB, int n) {
    __shared__ float meanS[D];
    int j = threadIdx.x;
    float s = 0.f;
    for (int b = 0; b < NB_MEAN; b++) s += g_part[b * D + j];
    meanS[j] = s / (float)n;
    __syncthreads();
    float a = glbB[j];
    #pragma unroll 4
    for (int k = 0; k < D; k++) a = fmaf(meanS[k], glbW[k * D + j], a);
    g_repr[j] = fmaxf(a, 0.f);
}

// ---------------- edge kernel ----------------
// Block = 128 threads (one per output column), TM=32 edges per block.
// Computes messages & attention from a single gathered edge-feature tile,
// then scatter-adds weighted messages into g_agg.
__global__ __launch_bounds__(128, 4)
void edge_kernel(const float* __restrict__ h,
                 const int* __restrict__ src,
                 const int* __restrict__ dst,
                 const float* __restrict__ msgW1, const float* __restrict__ msgB1,
                 const float* __restrict__ msgW2, const float* __restrict__ msgB2,
                 const float* __restrict__ attW1, const float* __restrict__ attB1,
                 const float* __restrict__ attW2, const float* __restrict__ attB2,
                 int E, int n)
{
    __shared__ float ef[TM][D2];   // 32 KB : [h[src] | h[dst]]
    __shared__ float hid[TM][D];   // 16 KB : hidden activations (reused)
    float* att_s = &ef[0][0];      // overlay: ef is dead when att_s is written

    int j  = threadIdx.x;
    int e0 = blockIdx.x * TM;

    // ---- gather edge features (float4, coalesced per row segment) ----
    for (int i = j; i < TM * 64; i += 128) {
        int m = i >> 6, q = i & 63;
        int e = e0 + m;
        int node = 0;
        if (e < E) node = (q < 32) ? src[e] : dst[e];
        if (node < 0) node = 0;
        if (node >= n) node = n - 1;
        float4 v = ((const float4*)(h + (size_t)node * D))[q & 31];
        ((float4*)&ef[m][0])[q] = v;
    }
    __syncthreads();

    // ---- msg layer 1: hid = relu(ef @ msgW1 + b1) ----
    float acc[TM];
    {
        float b1 = msgB1[j];
        #pragma unroll
        for (int m = 0; m < TM; m++) acc[m] = b1;
        for (int k = 0; k < D2; k += 4) {
            float w0 = msgW1[(k + 0) * D + j], w1 = msgW1[(k + 1) * D + j];
            float w2 = msgW1[(k + 2) * D + j], w3 = msgW1[(k + 3) * D + j];
            #pragma unroll
            for (int m = 0; m < TM; m++) {
                float4 e4 = *(const float4*)&ef[m][k];
                acc[m] = fmaf(e4.x, w0, fmaf(e4.y, w1, fmaf(e4.z, w2, fmaf(e4.w, w3, acc[m]))));
            }
        }
        #pragma unroll
        for (int m = 0; m < TM; m++) hid[m][j] = fmaxf(acc[m], 0.f);
    }
    __syncthreads();

    // ---- msg layer 2: msg = hid @ msgW2 + b2 (kept in registers) ----
    float msg[TM];
    {
        float b2 = msgB2[j];
        #pragma unroll
        for (int m = 0; m < TM; m++) msg[m] = b2;
        for (int k = 0; k < D; k += 4) {
            float w0 = msgW2[(k + 0) * D + j], w1 = msgW2[(k + 1) * D + j];
            float w2 = msgW2[(k + 2) * D + j], w3 = msgW2[(k + 3) * D + j];
            #pragma unroll
            for (int m = 0; m < TM; m++) {
                float4 h4 = *(const float4*)&hid[m][k];
                msg[m] = fmaf(h4.x, w0, fmaf(h4.y, w1, fmaf(h4.z, w2, fmaf(h4.w, w3, msg[m]))));
            }
        }
    }
    __syncthreads();   // everyone done reading hid before att overwrites it

    // ---- att layer 1: hid = relu(ef @ attW1 + b1) ----
    {
        float b1 = attB1[j];
        #pragma unroll
        for (int m = 0; m < TM; m++) acc[m] = b1;
        for (int k = 0; k < D2; k += 4) {
            float w0 = attW1[(k + 0) * D + j], w1 = attW1[(k + 1) * D + j];
            float w2 = attW1[(k + 2) * D + j], w3 = attW1[(k + 3) * D + j];
            #pragma unroll
            for (int m = 0; m < TM; m++) {
                float4 e4 = *(const float4*)&ef[m][k];
                acc[m] = fmaf(e4.x, w0, fmaf(e4.y, w1, fmaf(e4.z, w2, fmaf(e4.w, w3, acc[m]))));
            }
        }
        #pragma unroll
        for (int m = 0; m < TM; m++) hid[m][j] = fmaxf(acc[m], 0.f);
    }
    __syncthreads();   // hid ready; ef is now dead -> att_s overlay is safe

    // ---- att layer 2 + sigmoid: warp w handles edges 8w..8w+7 ----
    {
        int lane = j & 31, w = j >> 5;
        float awA = attW2[lane],      awB = attW2[lane + 32];
        float awC = attW2[lane + 64], awD = attW2[lane + 96];
        float ab2 = attB2[0];
        for (int mm = 0; mm < 8; mm++) {
            int m = w * 8 + mm;
            float s = hid[m][lane] * awA + hid[m][lane + 32] * awB
                    + hid[m][lane + 64] * awC + hid[m][lane + 96] * awD;
            #pragma unroll
            for (int off = 16; off > 0; off >>= 1)
                s += __shfl_xor_sync(0xffffffffu, s, off);
            if (lane == 0) att_s[m] = 1.f / (1.f + expf(-(s + ab2)));
        }
    }
    __syncthreads();

    // ---- weighted scatter-add (coalesced per row) ----
    #pragma unroll
    for (int m = 0; m < TM; m++) {
        int e = e0 + m;
        if (e < E) {
            int dn = dst[e];
            if (dn < 0) dn = 0;
            if (dn >= n) dn = n - 1;
            atomicAdd(&g_agg[(size_t)dn * D + j], msg[m] * att_s[m]);
        }
    }
}

// ---------------- node kernel ----------------
// out = MLP2([h | agg], upd) + h + global_repr
__global__ __launch_bounds__(128, 4)
void node_kernel(const float* __restrict__ h,
                 const float* __restrict__ updW1, const float* __restrict__ updB1,
                 const float* __restrict__ updW2, const float* __restrict__ updB2,
                 float* __restrict__ out, int n)
{
    __shared__ float ef[TM][D2];
    __shared__ float hid[TM][D];
    int j  = threadIdx.x;
    int n0 = blockIdx.x * TM;

    for (int i = j; i < TM * 64; i += 128) {
        int m = i >> 6, q = i & 63;
        int node = n0 + m; if (node >= n) node = n - 1;
        float4 v;
        if (q < 32) v = ((const float4*)(h + (size_t)node * D))[q];
        else        v = ((const float4*)(g_agg + (size_t)node * D))[q - 32];
        ((float4*)&ef[m][0])[q] = v;
    }
    __syncthreads();

    float acc[TM];
    {
        float b1 = updB1[j];
        #pragma unroll
        for (int m = 0; m < TM; m++) acc[m] = b1;
        for (int k = 0; k < D2; k += 4) {
            float w0 = updW1[(k + 0) * D + j], w1 = updW1[(k + 1) * D + j];
            float w2 = updW1[(k + 2) * D + j], w3 = updW1[(k + 3) * D + j];
            #pragma unroll
            for (int m = 0; m < TM; m++) {
                float4 e4 = *(const float4*)&ef[m][k];
                acc[m] = fmaf(e4.x, w0, fmaf(e4.y, w1, fmaf(e4.z, w2, fmaf(e4.w, w3, acc[m]))));
            }
        }
        #pragma unroll
        for (int m = 0; m < TM; m++) hid[m][j] = fmaxf(acc[m], 0.f);
    }
    __syncthreads();

    float o[TM];
    {
        float b2 = updB2[j];
        #pragma unroll
        for (int m = 0; m < TM; m++) o[m] = b2;
        for (int k = 0; k < D; k += 4) {
            float w0 = updW2[(k + 0) * D + j], w1 = updW2[(k + 1) * D + j];
            float w2 = updW2[(k + 2) * D + j], w3 = updW2[(k + 3) * D + j];
            #pragma unroll
            for (int m = 0; m < TM; m++) {
                float4 h4 = *(const float4*)&hid[m][k];
                o[m] = fmaf(h4.x, w0, fmaf(h4.y, w1, fmaf(h4.z, w2, fmaf(h4.w, w3, o[m]))));
            }
        }
    }

    float gr = g_repr[j];
    #pragma unroll
    for (int m = 0; m < TM; m++) {
        int node = n0 + m;
        if (node < n)
            out[(size_t)node * D + j] = o[m] + ef[m][j] + gr;   // new_h + h + global
    }
}

// ---------------- launch ----------------
extern "C" void kernel_launch(void* const* d_in, const int* in_sizes, int n_in,
                              void* d_out, int out_size)
{
    const float* x  = (const float*)d_in[0];
    const int*   ei = (const int*)d_in[1];     // edge_index materialized as int32 (JAX x64 off)
    const float* msgW1 = (const float*)d_in[2];
    const float* msgB1 = (const float*)d_in[3];
    const float* msgW2 = (const float*)d_in[4];
    const float* msgB2 = (const float*)d_in[5];
    const float* updW1 = (const float*)d_in[6];
    const float* updB1 = (const float*)d_in[7];
    const float* updW2 = (const float*)d_in[8];
    const float* updB2 = (const float*)d_in[9];
    const float* attW1 = (const float*)d_in[10];
    const float* attB1 = (const float*)d_in[11];
    const float* attW2 = (const float*)d_in[12];
    const float* attB2 = (const float*)d_in[13];
    const float* glbW  = (const float*)d_in[14];
    const float* glbB  = (const float*)d_in[15];

    int n = in_sizes[0] / D;
    int E = in_sizes[1] / 2;
    const int* src  = ei;
    const int* dstp = ei + E;
    float* out = (float*)d_out;

    float* h1 = nullptr;
    cudaGetSymbolAddress((void**)&h1, g_h1);

    int eb = (E + TM - 1) / TM;
    int nb = (n + TM - 1) / TM;

    // global representation (fixed across steps)
    mean1_kernel<<<NB_MEAN, 128>>>(x, n);
    repr_kernel<<<1, 128>>>(glbW, glbB, n);

    // step 1: h = x
    zero_agg_kernel<<<4096, 256>>>(n * D);
    edge_kernel<<<eb, 128>>>(x, src, dstp, msgW1, msgB1, msgW2, msgB2,
                             attW1, attB1, attW2, attB2, E, n);
    node_kernel<<<nb, 128>>>(x, updW1, updB1, updW2, updB2, h1, n);

    // step 2: h = g_h1, output -> d_out
    zero_agg_kernel<<<4096, 256>>>(n * D);
    edge_kernel<<<eb, 128>>>(h1, src, dstp, msgW1, msgB1, msgW2, msgB2,
                             attW1, attB1, attW2, attB2, E, n);
    node_kernel<<<nb, 128>>>(h1, updW1, updB1, updW2, updB2, out, n);
}

// round 4
// speedup vs baseline: 3.0560x; 3.0560x over previous
#include <cuda_runtime.h>
#include <math.h>

#define D   128
#define TM  32
#define NMAX 50000
#define NB_MEAN 200

// ---- scratch (device globals: allocation-free) ----
__device__ float g_h1[NMAX * D];    // h after step 1
__device__ float g_z[NMAX * D];     // scatter target: sum att*relu(u)
__device__ float g_satt[NMAX];      // scatter target: sum att
__device__ float g_Pt[NMAX * D];    // h @ msgW1_top
__device__ float g_Pb[NMAX * D];    // h @ msgW1_bot
__device__ float g_At[NMAX * D];    // h @ attW1_top
__device__ float g_Ab[NMAX * D];    // h @ attW1_bot
__device__ float g_Ht[NMAX * D];    // h @ updW1_top
__device__ float g_M[D * D];        // msgW2 @ updW1_bot (fused)
__device__ float g_bb[D];           // msgB2 @ updW1_bot
__device__ float g_part[NB_MEAN * D];
__device__ float g_repr[D];

// ---------------- small setup kernels ----------------
__global__ void zero_kernel(int n) {
    int total = n * D;
    for (int i = blockIdx.x * blockDim.x + threadIdx.x; i < total;
         i += gridDim.x * blockDim.x)
        g_z[i] = 0.f;
    for (int i = blockIdx.x * blockDim.x + threadIdx.x; i < n;
         i += gridDim.x * blockDim.x)
        g_satt[i] = 0.f;
}

__global__ void mean1_kernel(const float* __restrict__ x, int n) {
    int b = blockIdx.x, j = threadIdx.x;
    int per = (n + NB_MEAN - 1) / NB_MEAN;
    int r0 = b * per;
    int r1 = r0 + per; if (r1 > n) r1 = n;
    float s = 0.f;
    for (int r = r0; r < r1; r++) s += x[(size_t)r * D + j];
    g_part[b * D + j] = s;
}

__global__ void repr_kernel(const float* __restrict__ glbW,
                            const float* __restrict__ glbB, int n) {
    __shared__ float meanS[D];
    int j = threadIdx.x;
    float s = 0.f;
    for (int b = 0; b < NB_MEAN; b++) s += g_part[b * D + j];
    meanS[j] = s / (float)n;
    __syncthreads();
    float a = glbB[j];
    #pragma unroll 4
    for (int k = 0; k < D; k++) a = fmaf(meanS[k], glbW[k * D + j], a);
    g_repr[j] = fmaxf(a, 0.f);
}

// M[k][j] = sum_t msgW2[k][t] * updW1_bot[t][j];  bb[j] = sum_t msgB2[t]*updW1_bot[t][j]
__global__ void fuse_kernel(const float* __restrict__ msgW2,
                            const float* __restrict__ msgB2,
                            const float* __restrict__ updW1) {
    int k = blockIdx.x, j = threadIdx.x;
    float s = 0.f;
    for (int t = 0; t < D; t++)
        s = fmaf(msgW2[k * D + t], updW1[(D + t) * D + j], s);
    g_M[k * D + j] = s;
    if (k == 0) {
        float b = 0.f;
        for (int t = 0; t < D; t++)
            b = fmaf(msgB2[t], updW1[(D + t) * D + j], b);
        g_bb[j] = b;
    }
}

// ---------------- pre kernel: 5 node-side GEMMs sharing one h tile ----------------
#define GEMM_STORE(Wptr, OUT) { \
    float acc[TM]; \
    _Pragma("unroll") for (int m = 0; m < TM; m++) acc[m] = 0.f; \
    for (int k = 0; k < D; k += 4) { \
        float w0 = Wptr[(k+0)*D + j], w1 = Wptr[(k+1)*D + j]; \
        float w2 = Wptr[(k+2)*D + j], w3 = Wptr[(k+3)*D + j]; \
        _Pragma("unroll") for (int m = 0; m < TM; m++) { \
            float4 h4 = *(const float4*)&hs[m][k]; \
            acc[m] = fmaf(h4.x, w0, fmaf(h4.y, w1, fmaf(h4.z, w2, fmaf(h4.w, w3, acc[m])))); \
        } \
    } \
    _Pragma("unroll") for (int m = 0; m < TM; m++) { \
        int node = n0 + m; \
        if (node < n) OUT[(size_t)node * D + j] = acc[m]; \
    } }

__global__ __launch_bounds__(128, 4)
void pre_kernel(const float* __restrict__ h,
                const float* __restrict__ msgW1,
                const float* __restrict__ attW1,
                const float* __restrict__ updW1, int n)
{
    __shared__ float hs[TM][D];
    int j = threadIdx.x;
    int n0 = blockIdx.x * TM;

    for (int i = j; i < TM * 32; i += 128) {
        int m = i >> 5, q = i & 31;
        int node = n0 + m; if (node >= n) node = n - 1;
        ((float4*)&hs[m][0])[q] = ((const float4*)(h + (size_t)node * D))[q];
    }
    __syncthreads();

    GEMM_STORE(msgW1,           g_Pt)
    GEMM_STORE((msgW1 + D * D), g_Pb)
    GEMM_STORE(attW1,           g_At)
    GEMM_STORE((attW1 + D * D), g_Ab)
    GEMM_STORE(updW1,           g_Ht)
}

// ---------------- edge kernel: gather-add, attention, scatter (no GEMM) ----------------
__global__ __launch_bounds__(128, 4)
void edge_kernel(const int* __restrict__ src, const int* __restrict__ dst,
                 const float* __restrict__ msgB1,
                 const float* __restrict__ attB1,
                 const float* __restrict__ attW2,
                 const float* __restrict__ attB2, int E, int n)
{
    __shared__ float ap[TM][D];   // attention partials
    __shared__ float att_s[TM];
    __shared__ int sS[TM], sD[TM];

    int j  = threadIdx.x;
    int e0 = blockIdx.x * TM;

    if (j < TM) {
        int e = e0 + j;
        int s = 0, d = 0;
        if (e < E) { s = src[e]; d = dst[e]; }
        if (s < 0) s = 0; if (s >= n) s = n - 1;
        if (d < 0) d = 0; if (d >= n) d = n - 1;
        sS[j] = s; sD[j] = d;
    }
    __syncthreads();

    float b1 = msgB1[j], a1 = attB1[j], aw = attW2[j];
    float r[TM];
    #pragma unroll
    for (int m = 0; m < TM; m++) {
        int s = sS[m], d = sD[m];
        float um = g_Pt[(size_t)s * D + j] + g_Pb[(size_t)d * D + j] + b1;
        r[m] = fmaxf(um, 0.f);
        float ua = g_At[(size_t)s * D + j] + g_Ab[(size_t)d * D + j] + a1;
        ap[m][j] = fmaxf(ua, 0.f) * aw;
    }
    __syncthreads();

    // attention reduce: warp w handles edges 8w..8w+7
    {
        int lane = j & 31, w = j >> 5;
        float ab2 = attB2[0];
        for (int mm = 0; mm < 8; mm++) {
            int m = w * 8 + mm;
            float s4 = ap[m][lane] + ap[m][lane + 32] + ap[m][lane + 64] + ap[m][lane + 96];
            #pragma unroll
            for (int off = 16; off > 0; off >>= 1)
                s4 += __shfl_xor_sync(0xffffffffu, s4, off);
            if (lane == 0) att_s[m] = 1.f / (1.f + expf(-(s4 + ab2)));
        }
    }
    __syncthreads();

    // scatter: z += att*relu(u), satt += att
    #pragma unroll
    for (int m = 0; m < TM; m++) {
        int e = e0 + m;
        if (e < E)
            atomicAdd(&g_z[(size_t)sD[m] * D + j], att_s[m] * r[m]);
    }
    if (j < TM) {
        int e = e0 + j;
        if (e < E) atomicAdd(&g_satt[sD[j]], att_s[j]);
    }
}

// ---------------- update kernel ----------------
// hid = relu(Ht + z@M + satt*bb + updB1);  out = hid@updW2 + updB2 + h + repr
__global__ __launch_bounds__(128, 4)
void upd_kernel(const float* __restrict__ h,
                const float* __restrict__ updB1,
                const float* __restrict__ updW2,
                const float* __restrict__ updB2,
                float* __restrict__ out, int n)
{
    __shared__ float zs[TM][D];
    __shared__ float hid[TM][D];
    int j  = threadIdx.x;
    int n0 = blockIdx.x * TM;

    for (int i = j; i < TM * 32; i += 128) {
        int m = i >> 5, q = i & 31;
        int node = n0 + m; if (node >= n) node = n - 1;
        ((float4*)&zs[m][0])[q] = ((const float4*)(g_z + (size_t)node * D))[q];
    }
    __syncthreads();

    float b1 = updB1[j], bbj = g_bb[j];
    float acc[TM];
    #pragma unroll
    for (int m = 0; m < TM; m++) acc[m] = b1;
    for (int k = 0; k < D; k += 4) {
        float w0 = g_M[(k+0)*D + j], w1 = g_M[(k+1)*D + j];
        float w2 = g_M[(k+2)*D + j], w3 = g_M[(k+3)*D + j];
        #pragma unroll
        for (int m = 0; m < TM; m++) {
            float4 z4 = *(const float4*)&zs[m][k];
            acc[m] = fmaf(z4.x, w0, fmaf(z4.y, w1, fmaf(z4.z, w2, fmaf(z4.w, w3, acc[m]))));
        }
    }
    #pragma unroll
    for (int m = 0; m < TM; m++) {
        int node = n0 + m;
        int nc = node < n ? node : n - 1;
        float v = acc[m] + g_Ht[(size_t)nc * D + j] + g_satt[nc] * bbj;
        hid[m][j] = fmaxf(v, 0.f);
    }
    __syncthreads();

    float o[TM];
    float b2 = updB2[j];
    #pragma unroll
    for (int m = 0; m < TM; m++) o[m] = b2;
    for (int k = 0; k < D; k += 4) {
        float w0 = updW2[(k+0)*D + j], w1 = updW2[(k+1)*D + j];
        float w2 = updW2[(k+2)*D + j], w3 = updW2[(k+3)*D + j];
        #pragma unroll
        for (int m = 0; m < TM; m++) {
            float4 h4 = *(const float4*)&hid[m][k];
            o[m] = fmaf(h4.x, w0, fmaf(h4.y, w1, fmaf(h4.z, w2, fmaf(h4.w, w3, o[m]))));
        }
    }

    float gr = g_repr[j];
    #pragma unroll
    for (int m = 0; m < TM; m++) {
        int node = n0 + m;
        if (node < n)
            out[(size_t)node * D + j] = o[m] + h[(size_t)node * D + j] + gr;
    }
}

// ---------------- launch ----------------
extern "C" void kernel_launch(void* const* d_in, const int* in_sizes, int n_in,
                              void* d_out, int out_size)
{
    const float* x  = (const float*)d_in[0];
    const int*   ei = (const int*)d_in[1];     // int32 (JAX x64 disabled)
    const float* msgW1 = (const float*)d_in[2];
    const float* msgB1 = (const float*)d_in[3];
    const float* msgW2 = (const float*)d_in[4];
    const float* msgB2 = (const float*)d_in[5];
    const float* updW1 = (const float*)d_in[6];
    const float* updB1 = (const float*)d_in[7];
    const float* updW2 = (const float*)d_in[8];
    const float* updB2 = (const float*)d_in[9];
    const float* attW1 = (const float*)d_in[10];
    const float* attB1 = (const float*)d_in[11];
    const float* attW2 = (const float*)d_in[12];
    const float* attB2 = (const float*)d_in[13];
    const float* glbW  = (const float*)d_in[14];
    const float* glbB  = (const float*)d_in[15];

    int n = in_sizes[0] / D;
    int E = in_sizes[1] / 2;
    const int* src  = ei;
    const int* dstp = ei + E;
    float* out = (float*)d_out;

    float* h1 = nullptr;
    cudaGetSymbolAddress((void**)&h1, g_h1);

    int eb = (E + TM - 1) / TM;
    int nb = (n + TM - 1) / TM;

    // fixed across steps
    mean1_kernel<<<NB_MEAN, 128>>>(x, n);
    repr_kernel<<<1, 128>>>(glbW, glbB, n);
    fuse_kernel<<<D, 128>>>(msgW2, msgB2, updW1);

    // step 1: h = x
    pre_kernel<<<nb, 128>>>(x, msgW1, attW1, updW1, n);
    zero_kernel<<<4096, 256>>>(n);
    edge_kernel<<<eb, 128>>>(src, dstp, msgB1, attB1, attW2, attB2, E, n);
    upd_kernel<<<nb, 128>>>(x, updB1, updW2, updB2, h1, n);

    // step 2: h = g_h1, output -> d_out
    pre_kernel<<<nb, 128>>>(h1, msgW1, attW1, updW1, n);
    zero_kernel<<<4096, 256>>>(n);
    edge_kernel<<<eb, 128>>>(src, dstp, msgB1, attB1, attW2, attB2, E, n);
    upd_kernel<<<nb, 128>>>(h1, updB1, updW2, updB2, out, n);
}

// round 5
// speedup vs baseline: 3.2170x; 1.0527x over previous
#include <cuda_runtime.h>
#include <math.h>

#define D   128
#define TM  32
#define NMAX 50000
#define NB_MEAN 200

// ---- scratch (device globals: allocation-free) ----
__device__ float g_h1[NMAX * D];    // h after step 1
__device__ float g_z[NMAX * D];     // scatter target: sum att*relu(u)
__device__ float g_satt[NMAX];      // scatter target: sum att
__device__ float g_Pt[NMAX * D];    // h @ msgW1_top
__device__ float g_Pb[NMAX * D];    // h @ msgW1_bot
__device__ float g_At[NMAX * D];    // h @ attW1_top
__device__ float g_Ab[NMAX * D];    // h @ attW1_bot
__device__ float g_Ht[NMAX * D];    // h @ updW1_top
__device__ float g_M[D * D];        // msgW2 @ updW1_bot (fused)
__device__ float g_bb[D];           // msgB2 @ updW1_bot
__device__ float g_part[NB_MEAN * D];
__device__ float g_repr[D];

// ---------------- small setup kernels ----------------
__global__ void zero_kernel(int n) {
    int total = n * D;
    for (int i = blockIdx.x * blockDim.x + threadIdx.x; i < total;
         i += gridDim.x * blockDim.x)
        g_z[i] = 0.f;
    for (int i = blockIdx.x * blockDim.x + threadIdx.x; i < n;
         i += gridDim.x * blockDim.x)
        g_satt[i] = 0.f;
}

__global__ void mean1_kernel(const float* __restrict__ x, int n) {
    int b = blockIdx.x, j = threadIdx.x;
    int per = (n + NB_MEAN - 1) / NB_MEAN;
    int r0 = b * per;
    int r1 = r0 + per; if (r1 > n) r1 = n;
    float s = 0.f;
    for (int r = r0; r < r1; r++) s += x[(size_t)r * D + j];
    g_part[b * D + j] = s;
}

__global__ void repr_kernel(const float* __restrict__ glbW,
                            const float* __restrict__ glbB, int n) {
    __shared__ float meanS[D];
    int j = threadIdx.x;
    float s = 0.f;
    for (int b = 0; b < NB_MEAN; b++) s += g_part[b * D + j];
    meanS[j] = s / (float)n;
    __syncthreads();
    float a = glbB[j];
    #pragma unroll 4
    for (int k = 0; k < D; k++) a = fmaf(meanS[k], glbW[k * D + j], a);
    g_repr[j] = fmaxf(a, 0.f);
}

// M[k][j] = sum_t msgW2[k][t] * updW1_bot[t][j];  bb[j] = sum_t msgB2[t]*updW1_bot[t][j]
__global__ void fuse_kernel(const float* __restrict__ msgW2,
                            const float* __restrict__ msgB2,
                            const float* __restrict__ updW1) {
    int k = blockIdx.x, j = threadIdx.x;
    float s = 0.f;
    for (int t = 0; t < D; t++)
        s = fmaf(msgW2[k * D + t], updW1[(D + t) * D + j], s);
    g_M[k * D + j] = s;
    if (k == 0) {
        float b = 0.f;
        for (int t = 0; t < D; t++)
            b = fmaf(msgB2[t], updW1[(D + t) * D + j], b);
        g_bb[j] = b;
    }
}

// ---- 8x4 register-blocked GEMM core over a 32x128 tile in smem ----
// thread t: rg = t>>5 (row group, 8 rows), cg = t&31 (4 cols)
// acc[r] (float4) += hs[rg*8+r][k..k+3] dot W[k..k+3][4cg..4cg+3]
#define GEMM84(SRC_SMEM, Wptr) \
    _Pragma("unroll") for (int r = 0; r < 8; r++) acc[r] = make_float4(0.f,0.f,0.f,0.f); \
    for (int k = 0; k < D; k += 4) { \
        float4 w0 = *(const float4*)&Wptr[(k+0)*D + 4*cg]; \
        float4 w1 = *(const float4*)&Wptr[(k+1)*D + 4*cg]; \
        float4 w2 = *(const float4*)&Wptr[(k+2)*D + 4*cg]; \
        float4 w3 = *(const float4*)&Wptr[(k+3)*D + 4*cg]; \
        _Pragma("unroll") for (int r = 0; r < 8; r++) { \
            float4 h4 = *(const float4*)&SRC_SMEM[rg*8+r][k]; \
            acc[r].x = fmaf(h4.x, w0.x, fmaf(h4.y, w1.x, fmaf(h4.z, w2.x, fmaf(h4.w, w3.x, acc[r].x)))); \
            acc[r].y = fmaf(h4.x, w0.y, fmaf(h4.y, w1.y, fmaf(h4.z, w2.y, fmaf(h4.w, w3.y, acc[r].y)))); \
            acc[r].z = fmaf(h4.x, w0.z, fmaf(h4.y, w1.z, fmaf(h4.z, w2.z, fmaf(h4.w, w3.z, acc[r].z)))); \
            acc[r].w = fmaf(h4.x, w0.w, fmaf(h4.y, w1.w, fmaf(h4.z, w2.w, fmaf(h4.w, w3.w, acc[r].w)))); \
        } \
    }

// ---------------- pre kernel: 5 node-side GEMMs sharing one h tile ----------------
__global__ __launch_bounds__(128, 4)
void pre_kernel(const float* __restrict__ h,
                const float* __restrict__ msgW1,
                const float* __restrict__ attW1,
                const float* __restrict__ updW1, int n)
{
    __shared__ float hs[TM][D];
    int t = threadIdx.x;
    int cg = t & 31, rg = t >> 5;
    int n0 = blockIdx.x * TM;

    for (int i = t; i < TM * 32; i += 128) {
        int m = i >> 5, q = i & 31;
        int node = n0 + m; if (node >= n) node = n - 1;
        ((float4*)&hs[m][0])[q] = ((const float4*)(h + (size_t)node * D))[q];
    }
    __syncthreads();

    float4 acc[8];

    #define PRE_STORE(OUT) \
        _Pragma("unroll") for (int r = 0; r < 8; r++) { \
            int node = n0 + rg*8 + r; \
            if (node < n) *(float4*)&OUT[(size_t)node * D + 4*cg] = acc[r]; \
        }

    GEMM84(hs, msgW1)           PRE_STORE(g_Pt)
    GEMM84(hs, (msgW1 + D*D))   PRE_STORE(g_Pb)
    GEMM84(hs, attW1)           PRE_STORE(g_At)
    GEMM84(hs, (attW1 + D*D))   PRE_STORE(g_Ab)
    GEMM84(hs, updW1)           PRE_STORE(g_Ht)
    #undef PRE_STORE
}

// ---------------- edge kernel: gather-add, attention, scatter (no GEMM) ----------------
__global__ __launch_bounds__(128, 4)
void edge_kernel(const int* __restrict__ src, const int* __restrict__ dst,
                 const float* __restrict__ msgB1,
                 const float* __restrict__ attB1,
                 const float* __restrict__ attW2,
                 const float* __restrict__ attB2, int E, int n)
{
    __shared__ float ap[TM][D];   // attention partials
    __shared__ float att_s[TM];
    __shared__ int sS[TM], sD[TM];

    int j  = threadIdx.x;
    int e0 = blockIdx.x * TM;

    if (j < TM) {
        int e = e0 + j;
        int s = 0, d = 0;
        if (e < E) { s = src[e]; d = dst[e]; }
        if (s < 0) s = 0; if (s >= n) s = n - 1;
        if (d < 0) d = 0; if (d >= n) d = n - 1;
        sS[j] = s; sD[j] = d;
    }
    __syncthreads();

    float b1 = msgB1[j], a1 = attB1[j], aw = attW2[j];
    float r[TM];
    #pragma unroll
    for (int m = 0; m < TM; m++) {
        int s = sS[m], d = sD[m];
        float um = g_Pt[(size_t)s * D + j] + g_Pb[(size_t)d * D + j] + b1;
        r[m] = fmaxf(um, 0.f);
        float ua = g_At[(size_t)s * D + j] + g_Ab[(size_t)d * D + j] + a1;
        ap[m][j] = fmaxf(ua, 0.f) * aw;
    }
    __syncthreads();

    // attention reduce: warp w handles edges 8w..8w+7
    {
        int lane = j & 31, w = j >> 5;
        float ab2 = attB2[0];
        for (int mm = 0; mm < 8; mm++) {
            int m = w * 8 + mm;
            float s4 = ap[m][lane] + ap[m][lane + 32] + ap[m][lane + 64] + ap[m][lane + 96];
            #pragma unroll
            for (int off = 16; off > 0; off >>= 1)
                s4 += __shfl_xor_sync(0xffffffffu, s4, off);
            if (lane == 0) att_s[m] = 1.f / (1.f + expf(-(s4 + ab2)));
        }
    }
    __syncthreads();

    // scatter: z += att*relu(u), satt += att
    #pragma unroll
    for (int m = 0; m < TM; m++) {
        int e = e0 + m;
        if (e < E)
            atomicAdd(&g_z[(size_t)sD[m] * D + j], att_s[m] * r[m]);
    }
    if (j < TM) {
        int e = e0 + j;
        if (e < E) atomicAdd(&g_satt[sD[j]], att_s[j]);
    }
}

// ---------------- update kernel ----------------
// hid = relu(Ht + z@M + satt*bb + updB1);  out = hid@updW2 + updB2 + h + repr
__global__ __launch_bounds__(128, 4)
void upd_kernel(const float* __restrict__ h,
                const float* __restrict__ updB1,
                const float* __restrict__ updW2,
                const float* __restrict__ updB2,
                float* __restrict__ out, int n)
{
    __shared__ float zs[TM][D];
    __shared__ float hid[TM][D];
    int t = threadIdx.x;
    int cg = t & 31, rg = t >> 5;
    int n0 = blockIdx.x * TM;

    for (int i = t; i < TM * 32; i += 128) {
        int m = i >> 5, q = i & 31;
        int node = n0 + m; if (node >= n) node = n - 1;
        ((float4*)&zs[m][0])[q] = ((const float4*)(g_z + (size_t)node * D))[q];
    }
    __syncthreads();

    float4 acc[8];

    // phase A: hid = relu(z@M + Ht + satt*bb + b1)
    GEMM84(zs, g_M)
    {
        float4 b1 = *(const float4*)&updB1[4*cg];
        float4 bb = *(const float4*)&g_bb[4*cg];
        #pragma unroll
        for (int r = 0; r < 8; r++) {
            int node = n0 + rg*8 + r;
            int nc = node < n ? node : n - 1;
            float4 ht = *(const float4*)&g_Ht[(size_t)nc * D + 4*cg];
            float sa = g_satt[nc];
            float4 v;
            v.x = fmaxf(acc[r].x + ht.x + sa * bb.x + b1.x, 0.f);
            v.y = fmaxf(acc[r].y + ht.y + sa * bb.y + b1.y, 0.f);
            v.z = fmaxf(acc[r].z + ht.z + sa * bb.z + b1.z, 0.f);
            v.w = fmaxf(acc[r].w + ht.w + sa * bb.w + b1.w, 0.f);
            *(float4*)&hid[rg*8 + r][4*cg] = v;
        }
    }
    __syncthreads();

    // phase B: out = hid@updW2 + b2 + h + repr
    GEMM84(hid, updW2)
    {
        float4 b2 = *(const float4*)&updB2[4*cg];
        float4 gr = *(const float4*)&g_repr[4*cg];
        #pragma unroll
        for (int r = 0; r < 8; r++) {
            int node = n0 + rg*8 + r;
            if (node < n) {
                float4 hv = *(const float4*)&h[(size_t)node * D + 4*cg];
                float4 o;
                o.x = acc[r].x + b2.x + hv.x + gr.x;
                o.y = acc[r].y + b2.y + hv.y + gr.y;
                o.z = acc[r].z + b2.z + hv.z + gr.z;
                o.w = acc[r].w + b2.w + hv.w + gr.w;
                *(float4*)&out[(size_t)node * D + 4*cg] = o;
            }
        }
    }
}

// ---------------- launch ----------------
extern "C" void kernel_launch(void* const* d_in, const int* in_sizes, int n_in,
                              void* d_out, int out_size)
{
    const float* x  = (const float*)d_in[0];
    const int*   ei = (const int*)d_in[1];     // int32 (JAX x64 disabled)
    const float* msgW1 = (const float*)d_in[2];
    const float* msgB1 = (const float*)d_in[3];
    const float* msgW2 = (const float*)d_in[4];
    const float* msgB2 = (const float*)d_in[5];
    const float* updW1 = (const float*)d_in[6];
    const float* updB1 = (const float*)d_in[7];
    const float* updW2 = (const float*)d_in[8];
    const float* updB2 = (const float*)d_in[9];
    const float* attW1 = (const float*)d_in[10];
    const float* attB1 = (const float*)d_in[11];
    const float* attW2 = (const float*)d_in[12];
    const float* attB2 = (const float*)d_in[13];
    const float* glbW  = (const float*)d_in[14];
    const float* glbB  = (const float*)d_in[15];

    int n = in_sizes[0] / D;
    int E = in_sizes[1] / 2;
    const int* src  = ei;
    const int* dstp = ei + E;
    float* out = (float*)d_out;

    float* h1 = nullptr;
    cudaGetSymbolAddress((void**)&h1, g_h1);

    int eb = (E + TM - 1) / TM;
    int nb = (n + TM - 1) / TM;

    // fixed across steps
    mean1_kernel<<<NB_MEAN, 128>>>(x, n);
    repr_kernel<<<1, 128>>>(glbW, glbB, n);
    fuse_kernel<<<D, 128>>>(msgW2, msgB2, updW1);

    // step 1: h = x
    pre_kernel<<<nb, 128>>>(x, msgW1, attW1, updW1, n);
    zero_kernel<<<4096, 256>>>(n);
    edge_kernel<<<eb, 128>>>(src, dstp, msgB1, attB1, attW2, attB2, E, n);
    upd_kernel<<<nb, 128>>>(x, updB1, updW2, updB2, h1, n);

    // step 2: h = g_h1, output -> d_out
    pre_kernel<<<nb, 128>>>(h1, msgW1, attW1, updW1, n);
    zero_kernel<<<4096, 256>>>(n);
    edge_kernel<<<eb, 128>>>(src, dstp, msgB1, attB1, attW2, attB2, E, n);
    upd_kernel<<<nb, 128>>>(h1, updB1, updW2, updB2, out, n);
}

// round 6
// speedup vs baseline: 4.3843x; 1.3628x over previous
#include <cuda_runtime.h>
#include <cuda_fp16.h>
#include <math.h>

#define D   128
#define TM  32
#define NMAX 50000
#define NB_MEAN 200

// ---- scratch (device globals: allocation-free) ----
__device__ float  g_h1[NMAX * D];      // h after step 1
__device__ float  g_z[NMAX * D];       // scatter target: sum att*relu(u)
__device__ float  g_satt[NMAX];        // scatter target: sum att
__device__ __half g_srcp[NMAX * 256];  // per node: [Pt(128) | At(128)]  (h@msgW1t, h@attW1t)
__device__ __half g_dstp[NMAX * 256];  // per node: [Pb(128) | Ab(128)]  (h@msgW1b, h@attW1b)
__device__ float  g_Ht[NMAX * D];      // h @ updW1_top
__device__ float  g_M[D * D];          // msgW2 @ updW1_bot (fused)
__device__ float  g_bb[D];             // msgB2 @ updW1_bot
__device__ float  g_part[NB_MEAN * D];
__device__ float  g_repr[D];

// ---------------- small setup kernels ----------------
__global__ void mean1_kernel(const float* __restrict__ x, int n) {
    int b = blockIdx.x, j = threadIdx.x;
    int per = (n + NB_MEAN - 1) / NB_MEAN;
    int r0 = b * per;
    int r1 = r0 + per; if (r1 > n) r1 = n;
    float s = 0.f;
    for (int r = r0; r < r1; r++) s += x[(size_t)r * D + j];
    g_part[b * D + j] = s;
}

__global__ void repr_kernel(const float* __restrict__ glbW,
                            const float* __restrict__ glbB, int n) {
    __shared__ float meanS[D];
    int j = threadIdx.x;
    float s = 0.f;
    for (int b = 0; b < NB_MEAN; b++) s += g_part[b * D + j];
    meanS[j] = s / (float)n;
    __syncthreads();
    float a = glbB[j];
    #pragma unroll 4
    for (int k = 0; k < D; k++) a = fmaf(meanS[k], glbW[k * D + j], a);
    g_repr[j] = fmaxf(a, 0.f);
}

// M[k][j] = sum_t msgW2[k][t] * updW1_bot[t][j];  bb[j] = sum_t msgB2[t]*updW1_bot[t][j]
__global__ void fuse_kernel(const float* __restrict__ msgW2,
                            const float* __restrict__ msgB2,
                            const float* __restrict__ updW1) {
    int k = blockIdx.x, j = threadIdx.x;
    float s = 0.f;
    for (int t = 0; t < D; t++)
        s = fmaf(msgW2[k * D + t], updW1[(D + t) * D + j], s);
    g_M[k * D + j] = s;
    if (k == 0) {
        float b = 0.f;
        for (int t = 0; t < D; t++)
            b = fmaf(msgB2[t], updW1[(D + t) * D + j], b);
        g_bb[j] = b;
    }
}

// ---- 8x4 register-blocked GEMM core over a 32x128 tile in smem ----
// thread t: rg = t>>5 (row group, 8 rows), cg = t&31 (4 cols)
// unroll-4 on k: ptxas front-batches 16 weight LDG.128 -> MLP ~16 hides L2 latency
#define GEMM84(SRC_SMEM, Wptr) \
    _Pragma("unroll") for (int r = 0; r < 8; r++) acc[r] = make_float4(0.f,0.f,0.f,0.f); \
    _Pragma("unroll 4") \
    for (int k = 0; k < D; k += 4) { \
        float4 w0 = *(const float4*)&Wptr[(k+0)*D + 4*cg]; \
        float4 w1 = *(const float4*)&Wptr[(k+1)*D + 4*cg]; \
        float4 w2 = *(const float4*)&Wptr[(k+2)*D + 4*cg]; \
        float4 w3 = *(const float4*)&Wptr[(k+3)*D + 4*cg]; \
        _Pragma("unroll") for (int r = 0; r < 8; r++) { \
            float4 h4 = *(const float4*)&SRC_SMEM[rg*8+r][k]; \
            acc[r].x = fmaf(h4.x, w0.x, fmaf(h4.y, w1.x, fmaf(h4.z, w2.x, fmaf(h4.w, w3.x, acc[r].x)))); \
            acc[r].y = fmaf(h4.x, w0.y, fmaf(h4.y, w1.y, fmaf(h4.z, w2.y, fmaf(h4.w, w3.y, acc[r].y)))); \
            acc[r].z = fmaf(h4.x, w0.z, fmaf(h4.y, w1.z, fmaf(h4.z, w2.z, fmaf(h4.w, w3.z, acc[r].z)))); \
            acc[r].w = fmaf(h4.x, w0.w, fmaf(h4.y, w1.w, fmaf(h4.z, w2.w, fmaf(h4.w, w3.w, acc[r].w)))); \
        } \
    }

// ---------------- pre kernel: 5 node-side GEMMs sharing one h tile ----------------
__global__ __launch_bounds__(128, 4)
void pre_kernel(const float* __restrict__ h,
                const float* __restrict__ msgW1,
                const float* __restrict__ attW1,
                const float* __restrict__ updW1, int n)
{
    __shared__ float hs[TM][D];
    int t = threadIdx.x;
    int cg = t & 31, rg = t >> 5;
    int n0 = blockIdx.x * TM;

    for (int i = t; i < TM * 32; i += 128) {
        int m = i >> 5, q = i & 31;
        int node = n0 + m; if (node >= n) node = n - 1;
        ((float4*)&hs[m][0])[q] = ((const float4*)(h + (size_t)node * D))[q];
    }
    __syncthreads();

    float4 acc[8];

    // store float4 acc -> 4 halves (8B) at OUT + node*256 + OFF + 4*cg
    #define PRE_STORE_H(OUT, OFF) \
        _Pragma("unroll") for (int r = 0; r < 8; r++) { \
            int node = n0 + rg*8 + r; \
            if (node < n) { \
                __half2* p = (__half2*)(OUT + (size_t)node * 256 + (OFF) + 4*cg); \
                p[0] = __floats2half2_rn(acc[r].x, acc[r].y); \
                p[1] = __floats2half2_rn(acc[r].z, acc[r].w); \
            } \
        }

    GEMM84(hs, msgW1)           PRE_STORE_H(g_srcp, 0)
    GEMM84(hs, (msgW1 + D*D))   PRE_STORE_H(g_dstp, 0)
    GEMM84(hs, attW1)           PRE_STORE_H(g_srcp, 128)
    GEMM84(hs, (attW1 + D*D))   PRE_STORE_H(g_dstp, 128)
    #undef PRE_STORE_H

    GEMM84(hs, updW1)
    #pragma unroll
    for (int r = 0; r < 8; r++) {
        int node = n0 + rg*8 + r;
        if (node < n) *(float4*)&g_Ht[(size_t)node * D + 4*cg] = acc[r];
    }
}

// ---------------- edge kernel: fp16 gather-add, attention, scatter ----------------
__global__ __launch_bounds__(128, 4)
void edge_kernel(const int* __restrict__ src, const int* __restrict__ dst,
                 const float* __restrict__ msgB1,
                 const float* __restrict__ attB1,
                 const float* __restrict__ attW2,
                 const float* __restrict__ attB2, int E, int n)
{
    __shared__ float ap[TM][D];   // attention partials
    __shared__ float att_s[TM];
    __shared__ int sS[TM], sD[TM];

    int j  = threadIdx.x;
    int e0 = blockIdx.x * TM;

    if (j < TM) {
        int e = e0 + j;
        int s = 0, d = 0;
        if (e < E) { s = src[e]; d = dst[e]; }
        if (s < 0) s = 0; if (s >= n) s = n - 1;
        if (d < 0) d = 0; if (d >= n) d = n - 1;
        sS[j] = s; sD[j] = d;
    }
    __syncthreads();

    float b1 = msgB1[j], a1 = attB1[j], aw = attW2[j];
    float r[TM];
    #pragma unroll
    for (int m = 0; m < TM; m++) {
        const __half* sp = g_srcp + (size_t)sS[m] * 256;
        const __half* dp = g_dstp + (size_t)sD[m] * 256;
        float um = __half2float(sp[j]) + __half2float(dp[j]) + b1;
        r[m] = fmaxf(um, 0.f);
        float ua = __half2float(sp[128 + j]) + __half2float(dp[128 + j]) + a1;
        ap[m][j] = fmaxf(ua, 0.f) * aw;
    }
    __syncthreads();

    // attention reduce: warp w handles edges 8w..8w+7
    {
        int lane = j & 31, w = j >> 5;
        float ab2 = attB2[0];
        for (int mm = 0; mm < 8; mm++) {
            int m = w * 8 + mm;
            float s4 = ap[m][lane] + ap[m][lane + 32] + ap[m][lane + 64] + ap[m][lane + 96];
            #pragma unroll
            for (int off = 16; off > 0; off >>= 1)
                s4 += __shfl_xor_sync(0xffffffffu, s4, off);
            if (lane == 0) att_s[m] = 1.f / (1.f + expf(-(s4 + ab2)));
        }
    }
    __syncthreads();

    // scatter: z += att*relu(u), satt += att
    #pragma unroll
    for (int m = 0; m < TM; m++) {
        int e = e0 + m;
        if (e < E)
            atomicAdd(&g_z[(size_t)sD[m] * D + j], att_s[m] * r[m]);
    }
    if (j < TM) {
        int e = e0 + j;
        if (e < E) atomicAdd(&g_satt[sD[j]], att_s[j]);
    }
}

// ---------------- update kernel ----------------
// hid = relu(Ht + z@M + satt*bb + updB1);  out = hid@updW2 + updB2 + h + repr
__global__ __launch_bounds__(128, 4)
void upd_kernel(const float* __restrict__ h,
                const float* __restrict__ updB1,
                const float* __restrict__ updW2,
                const float* __restrict__ updB2,
                float* __restrict__ out, int n)
{
    __shared__ float zs[TM][D];
    __shared__ float hid[TM][D];
    int t = threadIdx.x;
    int cg = t & 31, rg = t >> 5;
    int n0 = blockIdx.x * TM;

    for (int i = t; i < TM * 32; i += 128) {
        int m = i >> 5, q = i & 31;
        int node = n0 + m; if (node >= n) node = n - 1;
        ((float4*)&zs[m][0])[q] = ((const float4*)(g_z + (size_t)node * D))[q];
    }
    __syncthreads();

    float4 acc[8];

    // phase A: hid = relu(z@M + Ht + satt*bb + b1)
    GEMM84(zs, g_M)
    {
        float4 b1 = *(const float4*)&updB1[4*cg];
        float4 bb = *(const float4*)&g_bb[4*cg];
        #pragma unroll
        for (int r = 0; r < 8; r++) {
            int node = n0 + rg*8 + r;
            int nc = node < n ? node : n - 1;
            float4 ht = *(const float4*)&g_Ht[(size_t)nc * D + 4*cg];
            float sa = g_satt[nc];
            float4 v;
            v.x = fmaxf(acc[r].x + ht.x + sa * bb.x + b1.x, 0.f);
            v.y = fmaxf(acc[r].y + ht.y + sa * bb.y + b1.y, 0.f);
            v.z = fmaxf(acc[r].z + ht.z + sa * bb.z + b1.z, 0.f);
            v.w = fmaxf(acc[r].w + ht.w + sa * bb.w + b1.w, 0.f);
            *(float4*)&hid[rg*8 + r][4*cg] = v;
        }
    }
    __syncthreads();

    // phase B: out = hid@updW2 + b2 + h + repr
    GEMM84(hid, updW2)
    {
        float4 b2 = *(const float4*)&updB2[4*cg];
        float4 gr = *(const float4*)&g_repr[4*cg];
        #pragma unroll
        for (int r = 0; r < 8; r++) {
            int node = n0 + rg*8 + r;
            if (node < n) {
                float4 hv = *(const float4*)&h[(size_t)node * D + 4*cg];
                float4 o;
                o.x = acc[r].x + b2.x + hv.x + gr.x;
                o.y = acc[r].y + b2.y + hv.y + gr.y;
                o.z = acc[r].z + b2.z + hv.z + gr.z;
                o.w = acc[r].w + b2.w + hv.w + gr.w;
                *(float4*)&out[(size_t)node * D + 4*cg] = o;
            }
        }
    }
}

// ---------------- launch ----------------
extern "C" void kernel_launch(void* const* d_in, const int* in_sizes, int n_in,
                              void* d_out, int out_size)
{
    const float* x  = (const float*)d_in[0];
    const int*   ei = (const int*)d_in[1];     // int32 (JAX x64 disabled)
    const float* msgW1 = (const float*)d_in[2];
    const float* msgB1 = (const float*)d_in[3];
    const float* msgW2 = (const float*)d_in[4];
    const float* msgB2 = (const float*)d_in[5];
    const float* updW1 = (const float*)d_in[6];
    const float* updB1 = (const float*)d_in[7];
    const float* updW2 = (const float*)d_in[8];
    const float* updB2 = (const float*)d_in[9];
    const float* attW1 = (const float*)d_in[10];
    const float* attB1 = (const float*)d_in[11];
    const float* attW2 = (const float*)d_in[12];
    const float* attB2 = (const float*)d_in[13];
    const float* glbW  = (const float*)d_in[14];
    const float* glbB  = (const float*)d_in[15];

    int n = in_sizes[0] / D;
    int E = in_sizes[1] / 2;
    const int* src  = ei;
    const int* dstp = ei + E;
    float* out = (float*)d_out;

    float* h1 = nullptr;  float* zP = nullptr;  float* saP = nullptr;
    cudaGetSymbolAddress((void**)&h1,  g_h1);
    cudaGetSymbolAddress((void**)&zP,  g_z);
    cudaGetSymbolAddress((void**)&saP, g_satt);

    int eb = (E + TM - 1) / TM;
    int nb = (n + TM - 1) / TM;

    // fixed across steps
    mean1_kernel<<<NB_MEAN, 128>>>(x, n);
    repr_kernel<<<1, 128>>>(glbW, glbB, n);
    fuse_kernel<<<D, 128>>>(msgW2, msgB2, updW1);

    // step 1: h = x
    pre_kernel<<<nb, 128>>>(x, msgW1, attW1, updW1, n);
    cudaMemsetAsync(zP, 0, (size_t)n * D * sizeof(float));
    cudaMemsetAsync(saP, 0, (size_t)n * sizeof(float));
    edge_kernel<<<eb, 128>>>(src, dstp, msgB1, attB1, attW2, attB2, E, n);
    upd_kernel<<<nb, 128>>>(x, updB1, updW2, updB2, h1, n);

    // step 2: h = g_h1, output -> d_out
    pre_kernel<<<nb, 128>>>(h1, msgW1, attW1, updW1, n);
    cudaMemsetAsync(zP, 0, (size_t)n * D * sizeof(float));
    cudaMemsetAsync(saP, 0, (size_t)n * sizeof(float));
    edge_kernel<<<eb, 128>>>(src, dstp, msgB1, attB1, attW2, attB2, E, n);
    upd_kernel<<<nb, 128>>>(h1, updB1, updW2, updB2, out, n);
}

// round 7
// speedup vs baseline: 5.4366x; 1.2400x over previous
#include <cuda_runtime.h>
#include <cuda_fp16.h>
#include <math.h>

#define D   128
#define TM  32
#define NMAX 50000
#define NB_MEAN 200

// ---- scratch (device globals: allocation-free) ----
__device__ float  g_h1[NMAX * D];      // h after step 1
__device__ __align__(16) float g_z[NMAX * D];   // scatter: sum att*relu(u)
__device__ float  g_satt[NMAX];        // scatter: sum att
// per node, 256 halves: interleaved pairs (Pt[j], At[j]) as __half2 at pair-index j
__device__ __align__(16) __half g_srcp[NMAX * 256];
// per node, interleaved pairs (Pb[j], Ab[j])
__device__ __align__(16) __half g_dstp[NMAX * 256];
__device__ float  g_Ht[NMAX * D];      // h @ updW1_top
__device__ float  g_M[D * D];          // msgW2 @ updW1_bot (fused)
__device__ float  g_bb[D];             // msgB2 @ updW1_bot
__device__ float  g_part[NB_MEAN * D];
__device__ float  g_repr[D];

__device__ __forceinline__ void red_add_v4(float* a, float4 v) {
    asm volatile("red.global.add.v4.f32 [%0], {%1,%2,%3,%4};"
                 :: "l"(a), "f"(v.x), "f"(v.y), "f"(v.z), "f"(v.w) : "memory");
}

// ---------------- small setup kernels ----------------
__global__ void mean1_kernel(const float* __restrict__ x, int n) {
    int b = blockIdx.x, j = threadIdx.x;
    int per = (n + NB_MEAN - 1) / NB_MEAN;
    int r0 = b * per;
    int r1 = r0 + per; if (r1 > n) r1 = n;
    float s = 0.f;
    for (int r = r0; r < r1; r++) s += x[(size_t)r * D + j];
    g_part[b * D + j] = s;
}

__global__ void repr_kernel(const float* __restrict__ glbW,
                            const float* __restrict__ glbB, int n) {
    __shared__ float meanS[D];
    int j = threadIdx.x;
    float s = 0.f;
    for (int b = 0; b < NB_MEAN; b++) s += g_part[b * D + j];
    meanS[j] = s / (float)n;
    __syncthreads();
    float a = glbB[j];
    #pragma unroll 4
    for (int k = 0; k < D; k++) a = fmaf(meanS[k], glbW[k * D + j], a);
    g_repr[j] = fmaxf(a, 0.f);
}

// M[k][j] = sum_t msgW2[k][t] * updW1_bot[t][j];  bb[j] = sum_t msgB2[t]*updW1_bot[t][j]
__global__ void fuse_kernel(const float* __restrict__ msgW2,
                            const float* __restrict__ msgB2,
                            const float* __restrict__ updW1) {
    int k = blockIdx.x, j = threadIdx.x;
    float s = 0.f;
    for (int t = 0; t < D; t++)
        s = fmaf(msgW2[k * D + t], updW1[(D + t) * D + j], s);
    g_M[k * D + j] = s;
    if (k == 0) {
        float b = 0.f;
        for (int t = 0; t < D; t++)
            b = fmaf(msgB2[t], updW1[(D + t) * D + j], b);
        g_bb[j] = b;
    }
}

// ---- 8x4 register-blocked GEMM core over a 32x128 tile in smem ----
#define GEMM84(SRC_SMEM, Wptr) \
    _Pragma("unroll") for (int r = 0; r < 8; r++) acc[r] = make_float4(0.f,0.f,0.f,0.f); \
    _Pragma("unroll 4") \
    for (int k = 0; k < D; k += 4) { \
        float4 w0 = *(const float4*)&Wptr[(k+0)*D + 4*cg]; \
        float4 w1 = *(const float4*)&Wptr[(k+1)*D + 4*cg]; \
        float4 w2 = *(const float4*)&Wptr[(k+2)*D + 4*cg]; \
        float4 w3 = *(const float4*)&Wptr[(k+3)*D + 4*cg]; \
        _Pragma("unroll") for (int r = 0; r < 8; r++) { \
            float4 h4 = *(const float4*)&SRC_SMEM[rg*8+r][k]; \
            acc[r].x = fmaf(h4.x, w0.x, fmaf(h4.y, w1.x, fmaf(h4.z, w2.x, fmaf(h4.w, w3.x, acc[r].x)))); \
            acc[r].y = fmaf(h4.x, w0.y, fmaf(h4.y, w1.y, fmaf(h4.z, w2.y, fmaf(h4.w, w3.y, acc[r].y)))); \
            acc[r].z = fmaf(h4.x, w0.z, fmaf(h4.y, w1.z, fmaf(h4.z, w2.z, fmaf(h4.w, w3.z, acc[r].z)))); \
            acc[r].w = fmaf(h4.x, w0.w, fmaf(h4.y, w1.w, fmaf(h4.z, w2.w, fmaf(h4.w, w3.w, acc[r].w)))); \
        } \
    }

// ---------------- pre kernel: 5 node-side GEMMs sharing one h tile ----------------
__global__ __launch_bounds__(128, 4)
void pre_kernel(const float* __restrict__ h,
                const float* __restrict__ msgW1,
                const float* __restrict__ attW1,
                const float* __restrict__ updW1, int n)
{
    __shared__ float hs[TM][D];
    int t = threadIdx.x;
    int cg = t & 31, rg = t >> 5;
    int n0 = blockIdx.x * TM;

    for (int i = t; i < TM * 32; i += 128) {
        int m = i >> 5, q = i & 31;
        int node = n0 + m; if (node >= n) node = n - 1;
        ((float4*)&hs[m][0])[q] = ((const float4*)(h + (size_t)node * D))[q];
    }
    __syncthreads();

    float4 acc[8];
    __half2 pk[8][2];

    #define PACK_ACC() \
        _Pragma("unroll") for (int r = 0; r < 8; r++) { \
            pk[r][0] = __floats2half2_rn(acc[r].x, acc[r].y); \
            pk[r][1] = __floats2half2_rn(acc[r].z, acc[r].w); \
        }
    // merge pk (msg) with current acc (att) -> interleaved half2 pairs, 16B store
    #define STORE_ILV(OUT) \
        _Pragma("unroll") for (int r = 0; r < 8; r++) { \
            int node = n0 + rg*8 + r; \
            if (node < n) { \
                __half2 a0 = __floats2half2_rn(acc[r].x, acc[r].y); \
                __half2 a1 = __floats2half2_rn(acc[r].z, acc[r].w); \
                __half2 o0 = __lows2half2 (pk[r][0], a0); \
                __half2 o1 = __highs2half2(pk[r][0], a0); \
                __half2 o2 = __lows2half2 (pk[r][1], a1); \
                __half2 o3 = __highs2half2(pk[r][1], a1); \
                uint4 u; \
                u.x = *(unsigned*)&o0; u.y = *(unsigned*)&o1; \
                u.z = *(unsigned*)&o2; u.w = *(unsigned*)&o3; \
                *(uint4*)((__half2*)(OUT + (size_t)node * 256) + 4*cg) = u; \
            } \
        }

    GEMM84(hs, msgW1)           PACK_ACC()
    GEMM84(hs, attW1)           STORE_ILV(g_srcp)
    GEMM84(hs, (msgW1 + D*D))   PACK_ACC()
    GEMM84(hs, (attW1 + D*D))   STORE_ILV(g_dstp)
    #undef PACK_ACC
    #undef STORE_ILV

    GEMM84(hs, updW1)
    #pragma unroll
    for (int r = 0; r < 8; r++) {
        int node = n0 + rg*8 + r;
        if (node < n) *(float4*)&g_Ht[(size_t)node * D + 4*cg] = acc[r];
    }
}

// ---------------- edge kernel: half2 gather, attention, v4 scatter ----------------
__global__ __launch_bounds__(128, 6)
void edge_kernel(const int* __restrict__ src, const int* __restrict__ dst,
                 const float* __restrict__ msgB1,
                 const float* __restrict__ attB1,
                 const float* __restrict__ attW2,
                 const float* __restrict__ attB2, int E, int n)
{
    __shared__ float ws[TM][D];   // att partials, then weighted messages
    __shared__ float att_s[TM];
    __shared__ int sS[TM], sD[TM];

    int j  = threadIdx.x;
    int e0 = blockIdx.x * TM;

    if (j < TM) {
        int e = e0 + j;
        int s = 0, d = 0;
        if (e < E) { s = src[e]; d = dst[e]; }
        if (s < 0) s = 0; if (s >= n) s = n - 1;
        if (d < 0) d = 0; if (d >= n) d = n - 1;
        sS[j] = s; sD[j] = d;
    }
    __syncthreads();

    const __half2* SP = (const __half2*)g_srcp;
    const __half2* DP = (const __half2*)g_dstp;
    float b1 = msgB1[j], a1 = attB1[j], aw = attW2[j];
    float r[TM];
    #pragma unroll
    for (int m = 0; m < TM; m++) {
        float2 sf = __half22float2(SP[(size_t)sS[m] * 128 + j]);
        float2 df = __half22float2(DP[(size_t)sD[m] * 128 + j]);
        r[m]     = fmaxf(sf.x + df.x + b1, 0.f);
        ws[m][j] = fmaxf(sf.y + df.y + a1, 0.f) * aw;
    }
    __syncthreads();

    // attention reduce: warp w handles edges 8w..8w+7
    {
        int lane = j & 31, w = j >> 5;
        float ab2 = attB2[0];
        for (int mm = 0; mm < 8; mm++) {
            int m = w * 8 + mm;
            float s4 = ws[m][lane] + ws[m][lane + 32] + ws[m][lane + 64] + ws[m][lane + 96];
            #pragma unroll
            for (int off = 16; off > 0; off >>= 1)
                s4 += __shfl_xor_sync(0xffffffffu, s4, off);
            if (lane == 0) att_s[m] = 1.f / (1.f + expf(-(s4 + ab2)));
        }
    }
    __syncthreads();

    // weighted messages into smem
    #pragma unroll
    for (int m = 0; m < TM; m++) ws[m][j] = att_s[m] * r[m];
    if (j < TM) {
        int e = e0 + j;
        if (e < E) atomicAdd(&g_satt[sD[j]], att_s[j]);
    }
    __syncthreads();

    // vector scatter: 8 red.v4 per thread
    #pragma unroll
    for (int i = j; i < TM * 32; i += 128) {
        int m = i >> 5, q = i & 31;
        int e = e0 + m;
        if (e < E) {
            float4 v = *(float4*)&ws[m][4 * q];
            red_add_v4(&g_z[(size_t)sD[m] * D + 4 * q], v);
        }
    }
}

// ---------------- update kernel ----------------
// hid = relu(Ht + z@M + satt*bb + updB1);  out = hid@updW2 + updB2 + h + repr
__global__ __launch_bounds__(128, 4)
void upd_kernel(const float* __restrict__ h,
                const float* __restrict__ updB1,
                const float* __restrict__ updW2,
                const float* __restrict__ updB2,
                float* __restrict__ out, int n)
{
    __shared__ float zs[TM][D];
    __shared__ float hid[TM][D];
    int t = threadIdx.x;
    int cg = t & 31, rg = t >> 5;
    int n0 = blockIdx.x * TM;

    for (int i = t; i < TM * 32; i += 128) {
        int m = i >> 5, q = i & 31;
        int node = n0 + m; if (node >= n) node = n - 1;
        ((float4*)&zs[m][0])[q] = ((const float4*)(g_z + (size_t)node * D))[q];
    }
    __syncthreads();

    float4 acc[8];

    // phase A: hid = relu(z@M + Ht + satt*bb + b1)
    GEMM84(zs, g_M)
    {
        float4 b1 = *(const float4*)&updB1[4*cg];
        float4 bb = *(const float4*)&g_bb[4*cg];
        #pragma unroll
        for (int r = 0; r < 8; r++) {
            int node = n0 + rg*8 + r;
            int nc = node < n ? node : n - 1;
            float4 ht = *(const float4*)&g_Ht[(size_t)nc * D + 4*cg];
            float sa = g_satt[nc];
            float4 v;
            v.x = fmaxf(acc[r].x + ht.x + sa * bb.x + b1.x, 0.f);
            v.y = fmaxf(acc[r].y + ht.y + sa * bb.y + b1.y, 0.f);
            v.z = fmaxf(acc[r].z + ht.z + sa * bb.z + b1.z, 0.f);
            v.w = fmaxf(acc[r].w + ht.w + sa * bb.w + b1.w, 0.f);
            *(float4*)&hid[rg*8 + r][4*cg] = v;
        }
    }
    __syncthreads();

    // phase B: out = hid@updW2 + b2 + h + repr
    GEMM84(hid, updW2)
    {
        float4 b2 = *(const float4*)&updB2[4*cg];
        float4 gr = *(const float4*)&g_repr[4*cg];
        #pragma unroll
        for (int r = 0; r < 8; r++) {
            int node = n0 + rg*8 + r;
            if (node < n) {
                float4 hv = *(const float4*)&h[(size_t)node * D + 4*cg];
                float4 o;
                o.x = acc[r].x + b2.x + hv.x + gr.x;
                o.y = acc[r].y + b2.y + hv.y + gr.y;
                o.z = acc[r].z + b2.z + hv.z + gr.z;
                o.w = acc[r].w + b2.w + hv.w + gr.w;
                *(float4*)&out[(size_t)node * D + 4*cg] = o;
            }
        }
    }
}

// ---------------- launch ----------------
extern "C" void kernel_launch(void* const* d_in, const int* in_sizes, int n_in,
                              void* d_out, int out_size)
{
    const float* x  = (const float*)d_in[0];
    const int*   ei = (const int*)d_in[1];     // int32 (JAX x64 disabled)
    const float* msgW1 = (const float*)d_in[2];
    const float* msgB1 = (const float*)d_in[3];
    const float* msgW2 = (const float*)d_in[4];
    const float* msgB2 = (const float*)d_in[5];
    const float* updW1 = (const float*)d_in[6];
    const float* updB1 = (const float*)d_in[7];
    const float* updW2 = (const float*)d_in[8];
    const float* updB2 = (const float*)d_in[9];
    const float* attW1 = (const float*)d_in[10];
    const float* attB1 = (const float*)d_in[11];
    const float* attW2 = (const float*)d_in[12];
    const float* attB2 = (const float*)d_in[13];
    const float* glbW  = (const float*)d_in[14];
    const float* glbB  = (const float*)d_in[15];

    int n = in_sizes[0] / D;
    int E = in_sizes[1] / 2;
    const int* src  = ei;
    const int* dstp = ei + E;
    float* out = (float*)d_out;

    float* h1 = nullptr;  float* zP = nullptr;  float* saP = nullptr;
    cudaGetSymbolAddress((void**)&h1,  g_h1);
    cudaGetSymbolAddress((void**)&zP,  g_z);
    cudaGetSymbolAddress((void**)&saP, g_satt);

    int eb = (E + TM - 1) / TM;
    int nb = (n + TM - 1) / TM;

    // fixed across steps
    mean1_kernel<<<NB_MEAN, 128>>>(x, n);
    repr_kernel<<<1, 128>>>(glbW, glbB, n);
    fuse_kernel<<<D, 128>>>(msgW2, msgB2, updW1);

    // step 1: h = x
    pre_kernel<<<nb, 128>>>(x, msgW1, attW1, updW1, n);
    cudaMemsetAsync(zP, 0, (size_t)n * D * sizeof(float));
    cudaMemsetAsync(saP, 0, (size_t)n * sizeof(float));
    edge_kernel<<<eb, 128>>>(src, dstp, msgB1, attB1, attW2, attB2, E, n);
    upd_kernel<<<nb, 128>>>(x, updB1, updW2, updB2, h1, n);

    // step 2: h = g_h1, output -> d_out
    pre_kernel<<<nb, 128>>>(h1, msgW1, attW1, updW1, n);
    cudaMemsetAsync(zP, 0, (size_t)n * D * sizeof(float));
    cudaMemsetAsync(saP, 0, (size_t)n * sizeof(float));
    edge_kernel<<<eb, 128>>>(src, dstp, msgB1, attB1, attW2, attB2, E, n);
    upd_kernel<<<nb, 128>>>(h1, updB1, updW2, updB2, out, n);
}

// round 8
// speedup vs baseline: 7.3432x; 1.3507x over previous
#include <cuda_runtime.h>
#include <cuda_fp16.h>
#include <math.h>

#define D   128
#define TM  32
#define NMAX 50000
#define NB_MEAN 200

// ---- scratch (device globals: allocation-free) ----
__device__ float  g_h1[NMAX * D];      // h after step 1
__device__ __align__(16) float g_z[NMAX * D];   // scatter: sum att*relu(u)
__device__ float  g_satt[NMAX];        // scatter: sum att
// per node, 256 halves: interleaved pairs (Pt[j], At[j]) as __half2 at pair-index j
__device__ __align__(16) __half g_srcp[NMAX * 256];
// per node, interleaved pairs (Pb[j], Ab[j])
__device__ __align__(16) __half g_dstp[NMAX * 256];
__device__ float  g_Ht[NMAX * D];      // h @ updW1_top
__device__ float  g_M[D * D];          // msgW2 @ updW1_bot (fused, fp32)
__device__ float  g_bb[D];             // msgB2 @ updW1_bot
__device__ float  g_part[NB_MEAN * D];
__device__ float  g_repr[D];
// fp16 transposed weights, [n][k] row-major, 7 matrices:
// 0:msgW1top 1:attW1top 2:msgW1bot 3:attW1bot 4:updW1top 5:M 6:updW2
__device__ __align__(16) __half g_WT[7 * D * D];

__device__ __forceinline__ void red_add_v4(float* a, float4 v) {
    asm volatile("red.global.add.v4.f32 [%0], {%1,%2,%3,%4};"
                 :: "l"(a), "f"(v.x), "f"(v.y), "f"(v.z), "f"(v.w) : "memory");
}

__device__ __forceinline__ void mma16816(float* d, const unsigned* a,
                                         unsigned b0, unsigned b1) {
    asm volatile(
        "mma.sync.aligned.m16n8k16.row.col.f32.f16.f16.f32 "
        "{%0,%1,%2,%3}, {%4,%5,%6,%7}, {%8,%9}, {%0,%1,%2,%3};"
        : "+f"(d[0]), "+f"(d[1]), "+f"(d[2]), "+f"(d[3])
        : "r"(a[0]), "r"(a[1]), "r"(a[2]), "r"(a[3]), "r"(b0), "r"(b1));
}

// ---------------- small setup kernels ----------------
__global__ void mean1_kernel(const float* __restrict__ x, int n) {
    int b = blockIdx.x, j = threadIdx.x;
    int per = (n + NB_MEAN - 1) / NB_MEAN;
    int r0 = b * per;
    int r1 = r0 + per; if (r1 > n) r1 = n;
    float s = 0.f;
    for (int r = r0; r < r1; r++) s += x[(size_t)r * D + j];
    g_part[b * D + j] = s;
}

__global__ void repr_kernel(const float* __restrict__ glbW,
                            const float* __restrict__ glbB, int n) {
    __shared__ float meanS[D];
    int j = threadIdx.x;
    float s = 0.f;
    for (int b = 0; b < NB_MEAN; b++) s += g_part[b * D + j];
    meanS[j] = s / (float)n;
    __syncthreads();
    float a = glbB[j];
    #pragma unroll 4
    for (int k = 0; k < D; k++) a = fmaf(meanS[k], glbW[k * D + j], a);
    g_repr[j] = fmaxf(a, 0.f);
}

// M[k][j] = sum_t msgW2[k][t] * updW1_bot[t][j];  bb[j] = sum_t msgB2[t]*updW1_bot[t][j]
__global__ void fuse_kernel(const float* __restrict__ msgW2,
                            const float* __restrict__ msgB2,
                            const float* __restrict__ updW1) {
    int k = blockIdx.x, j = threadIdx.x;
    float s = 0.f;
    for (int t = 0; t < D; t++)
        s = fmaf(msgW2[k * D + t], updW1[(D + t) * D + j], s);
    g_M[k * D + j] = s;
    if (k == 0) {
        float b = 0.f;
        for (int t = 0; t < D; t++)
            b = fmaf(msgB2[t], updW1[(D + t) * D + j], b);
        g_bb[j] = b;
    }
}

// transpose + fp16-convert the 7 weight matrices into g_WT  (runs after fuse_kernel)
__global__ void wconv_kernel(const float* __restrict__ msgW1,
                             const float* __restrict__ attW1,
                             const float* __restrict__ updW1,
                             const float* __restrict__ updW2) {
    int nrow = blockIdx.x;   // output feature n
    int k    = threadIdx.x;  // reduction index k
    int m    = blockIdx.y;
    float v;
    switch (m) {
        case 0: v = msgW1[k * D + nrow]; break;
        case 1: v = attW1[k * D + nrow]; break;
        case 2: v = msgW1[(D + k) * D + nrow]; break;
        case 3: v = attW1[(D + k) * D + nrow]; break;
        case 4: v = updW1[k * D + nrow]; break;
        case 5: v = g_M[k * D + nrow]; break;
        default: v = updW2[k * D + nrow]; break;
    }
    g_WT[m * D * D + nrow * D + k] = __float2half(v);
}

// ---- warp-level fp16 MMA GEMM over a 32x128 tile (SRC fp16 smem, stride 136) ----
// warp w owns cols [32w, 32w+32); thread: g=lane>>2, t=lane&3
// ACC[mt][nt][4]: mt in {0,1} (rows 16mt..16mt+15), nt in {0..3} (cols 8nt..)
#define MMA_GEMM(ACC, WI, SRC) { \
    _Pragma("unroll") for (int mt_ = 0; mt_ < 2; mt_++) \
    _Pragma("unroll") for (int nt_ = 0; nt_ < 4; nt_++) \
    _Pragma("unroll") for (int e_ = 0; e_ < 4; e_++) ACC[mt_][nt_][e_] = 0.f; \
    const __half* WT_ = g_WT + (WI) * D * D; \
    _Pragma("unroll") \
    for (int kc = 0; kc < 8; kc++) { \
        unsigned a0[4], a1[4]; \
        a0[0] = *(const unsigned*)&SRC[g][16*kc + 2*t]; \
        a0[1] = *(const unsigned*)&SRC[g + 8][16*kc + 2*t]; \
        a0[2] = *(const unsigned*)&SRC[g][16*kc + 2*t + 8]; \
        a0[3] = *(const unsigned*)&SRC[g + 8][16*kc + 2*t + 8]; \
        a1[0] = *(const unsigned*)&SRC[16 + g][16*kc + 2*t]; \
        a1[1] = *(const unsigned*)&SRC[24 + g][16*kc + 2*t]; \
        a1[2] = *(const unsigned*)&SRC[16 + g][16*kc + 2*t + 8]; \
        a1[3] = *(const unsigned*)&SRC[24 + g][16*kc + 2*t + 8]; \
        _Pragma("unroll") \
        for (int nt = 0; nt < 4; nt++) { \
            int nrow_ = 32*w + 8*nt + g; \
            unsigned b0 = *(const unsigned*)&WT_[nrow_ * D + 16*kc + 2*t]; \
            unsigned b1 = *(const unsigned*)&WT_[nrow_ * D + 16*kc + 2*t + 8]; \
            mma16816(ACC[0][nt], a0, b0, b1); \
            mma16816(ACC[1][nt], a1, b0, b1); \
        } \
    } }

// ---------------- pre kernel: 5 GEMMs via tensor cores ----------------
__global__ __launch_bounds__(128, 4)
void pre_kernel(const float* __restrict__ h, int n)
{
    __shared__ __half hsf[TM][136];
    int tid = threadIdx.x, lane = tid & 31, w = tid >> 5;
    int g = lane >> 2, t = lane & 3;
    int n0 = blockIdx.x * TM;

    for (int i = tid; i < TM * 32; i += 128) {
        int m = i >> 5, q = i & 31;
        int node = n0 + m; if (node >= n) node = n - 1;
        float4 v = ((const float4*)(h + (size_t)node * D))[q];
        *(__half2*)&hsf[m][4*q]     = __floats2half2_rn(v.x, v.y);
        *(__half2*)&hsf[m][4*q + 2] = __floats2half2_rn(v.z, v.w);
    }
    __syncthreads();

    float accP[2][4][4], accA[2][4][4];

    // interleaved (P,A) half2-pair store matching edge-kernel layout
    #define STORE_ILV(OUT) \
        _Pragma("unroll") for (int mt = 0; mt < 2; mt++) \
        _Pragma("unroll") for (int nt = 0; nt < 4; nt++) { \
            int row = 16*mt + g, col = 32*w + 8*nt + 2*t; \
            int node = n0 + row; \
            if (node < n) { \
                __half2 p = __floats2half2_rn(accP[mt][nt][0], accP[mt][nt][1]); \
                __half2 a = __floats2half2_rn(accA[mt][nt][0], accA[mt][nt][1]); \
                __half2 o0 = __lows2half2(p, a), o1 = __highs2half2(p, a); \
                uint2 u; u.x = *(unsigned*)&o0; u.y = *(unsigned*)&o1; \
                *(uint2*)(OUT + (size_t)node * 256 + 2*col) = u; \
            } \
            int node2 = n0 + row + 8; \
            if (node2 < n) { \
                __half2 p = __floats2half2_rn(accP[mt][nt][2], accP[mt][nt][3]); \
                __half2 a = __floats2half2_rn(accA[mt][nt][2], accA[mt][nt][3]); \
                __half2 o0 = __lows2half2(p, a), o1 = __highs2half2(p, a); \
                uint2 u; u.x = *(unsigned*)&o0; u.y = *(unsigned*)&o1; \
                *(uint2*)(OUT + (size_t)node2 * 256 + 2*col) = u; \
            } \
        }

    MMA_GEMM(accP, 0, hsf)   // h @ msgW1_top
    MMA_GEMM(accA, 1, hsf)   // h @ attW1_top
    STORE_ILV(g_srcp)
    MMA_GEMM(accP, 2, hsf)   // h @ msgW1_bot
    MMA_GEMM(accA, 3, hsf)   // h @ attW1_bot
    STORE_ILV(g_dstp)
    #undef STORE_ILV

    MMA_GEMM(accP, 4, hsf)   // h @ updW1_top -> Ht (fp32)
    #pragma unroll
    for (int mt = 0; mt < 2; mt++)
    #pragma unroll
    for (int nt = 0; nt < 4; nt++) {
        int row = 16*mt + g, col = 32*w + 8*nt + 2*t;
        int node = n0 + row;
        if (node < n) {
            float2 v = make_float2(accP[mt][nt][0], accP[mt][nt][1]);
            *(float2*)&g_Ht[(size_t)node * D + col] = v;
        }
        int node2 = n0 + row + 8;
        if (node2 < n) {
            float2 v = make_float2(accP[mt][nt][2], accP[mt][nt][3]);
            *(float2*)&g_Ht[(size_t)node2 * D + col] = v;
        }
    }
}

// ---------------- edge kernel: half2 gather, attention, v4 scatter ----------------
__global__ __launch_bounds__(128, 6)
void edge_kernel(const int* __restrict__ src, const int* __restrict__ dst,
                 const float* __restrict__ msgB1,
                 const float* __restrict__ attB1,
                 const float* __restrict__ attW2,
                 const float* __restrict__ attB2, int E, int n)
{
    __shared__ float ws[TM][D];   // att partials, then weighted messages
    __shared__ float att_s[TM];
    __shared__ int sS[TM], sD[TM];

    int j  = threadIdx.x;
    int e0 = blockIdx.x * TM;

    if (j < TM) {
        int e = e0 + j;
        int s = 0, d = 0;
        if (e < E) { s = src[e]; d = dst[e]; }
        if (s < 0) s = 0; if (s >= n) s = n - 1;
        if (d < 0) d = 0; if (d >= n) d = n - 1;
        sS[j] = s; sD[j] = d;
    }
    __syncthreads();

    const __half2* SP = (const __half2*)g_srcp;
    const __half2* DP = (const __half2*)g_dstp;
    float b1 = msgB1[j], a1 = attB1[j], aw = attW2[j];
    float r[TM];
    #pragma unroll
    for (int m = 0; m < TM; m++) {
        float2 sf = __half22float2(SP[(size_t)sS[m] * 128 + j]);
        float2 df = __half22float2(DP[(size_t)sD[m] * 128 + j]);
        r[m]     = fmaxf(sf.x + df.x + b1, 0.f);
        ws[m][j] = fmaxf(sf.y + df.y + a1, 0.f) * aw;
    }
    __syncthreads();

    {
        int lane = j & 31, w = j >> 5;
        float ab2 = attB2[0];
        for (int mm = 0; mm < 8; mm++) {
            int m = w * 8 + mm;
            float s4 = ws[m][lane] + ws[m][lane + 32] + ws[m][lane + 64] + ws[m][lane + 96];
            #pragma unroll
            for (int off = 16; off > 0; off >>= 1)
                s4 += __shfl_xor_sync(0xffffffffu, s4, off);
            if (lane == 0) att_s[m] = 1.f / (1.f + expf(-(s4 + ab2)));
        }
    }
    __syncthreads();

    #pragma unroll
    for (int m = 0; m < TM; m++) ws[m][j] = att_s[m] * r[m];
    if (j < TM) {
        int e = e0 + j;
        if (e < E) atomicAdd(&g_satt[sD[j]], att_s[j]);
    }
    __syncthreads();

    #pragma unroll
    for (int i = j; i < TM * 32; i += 128) {
        int m = i >> 5, q = i & 31;
        int e = e0 + m;
        if (e < E) {
            float4 v = *(float4*)&ws[m][4 * q];
            red_add_v4(&g_z[(size_t)sD[m] * D + 4 * q], v);
        }
    }
}

// ---------------- update kernel: 2 GEMMs via tensor cores ----------------
__global__ __launch_bounds__(128, 4)
void upd_kernel(const float* __restrict__ h,
                const float* __restrict__ updB1,
                const float* __restrict__ updB2,
                float* __restrict__ out, int n)
{
    __shared__ __half zsf[TM][136];
    __shared__ __half hid[TM][136];
    int tid = threadIdx.x, lane = tid & 31, w = tid >> 5;
    int g = lane >> 2, t = lane & 3;
    int n0 = blockIdx.x * TM;

    for (int i = tid; i < TM * 32; i += 128) {
        int m = i >> 5, q = i & 31;
        int node = n0 + m; if (node >= n) node = n - 1;
        float4 v = ((const float4*)(g_z + (size_t)node * D))[q];
        *(__half2*)&zsf[m][4*q]     = __floats2half2_rn(v.x, v.y);
        *(__half2*)&zsf[m][4*q + 2] = __floats2half2_rn(v.z, v.w);
    }
    __syncthreads();

    float acc[2][4][4];

    // phase A: hid = relu(z@M + Ht + satt*bb + b1)
    MMA_GEMM(acc, 5, zsf)
    #pragma unroll
    for (int mt = 0; mt < 2; mt++)
    #pragma unroll
    for (int nt = 0; nt < 4; nt++) {
        int row = 16*mt + g, col = 32*w + 8*nt + 2*t;
        float2 bb = *(const float2*)&g_bb[col];
        float2 b1 = *(const float2*)&updB1[col];
        {
            int node = n0 + row;
            int nc = node < n ? node : n - 1;
            float2 ht = *(const float2*)&g_Ht[(size_t)nc * D + col];
            float sa = g_satt[nc];
            float v0 = fmaxf(acc[mt][nt][0] + ht.x + sa * bb.x + b1.x, 0.f);
            float v1 = fmaxf(acc[mt][nt][1] + ht.y + sa * bb.y + b1.y, 0.f);
            *(__half2*)&hid[row][col] = __floats2half2_rn(v0, v1);
        }
        {
            int node = n0 + row + 8;
            int nc = node < n ? node : n - 1;
            float2 ht = *(const float2*)&g_Ht[(size_t)nc * D + col];
            float sa = g_satt[nc];
            float v0 = fmaxf(acc[mt][nt][2] + ht.x + sa * bb.x + b1.x, 0.f);
            float v1 = fmaxf(acc[mt][nt][3] + ht.y + sa * bb.y + b1.y, 0.f);
            *(__half2*)&hid[row + 8][col] = __floats2half2_rn(v0, v1);
        }
    }
    __syncthreads();

    // phase B: out = hid@updW2 + b2 + h + repr
    MMA_GEMM(acc, 6, hid)
    #pragma unroll
    for (int mt = 0; mt < 2; mt++)
    #pragma unroll
    for (int nt = 0; nt < 4; nt++) {
        int row = 16*mt + g, col = 32*w + 8*nt + 2*t;
        float2 b2 = *(const float2*)&updB2[col];
        float2 gr = *(const float2*)&g_repr[col];
        {
            int node = n0 + row;
            if (node < n) {
                float2 hv = *(const float2*)&h[(size_t)node * D + col];
                float2 o = make_float2(acc[mt][nt][0] + b2.x + hv.x + gr.x,
                                       acc[mt][nt][1] + b2.y + hv.y + gr.y);
                *(float2*)&out[(size_t)node * D + col] = o;
            }
        }
        {
            int node = n0 + row + 8;
            if (node < n) {
                float2 hv = *(const float2*)&h[(size_t)node * D + col];
                float2 o = make_float2(acc[mt][nt][2] + b2.x + hv.x + gr.x,
                                       acc[mt][nt][3] + b2.y + hv.y + gr.y);
                *(float2*)&out[(size_t)node * D + col] = o;
            }
        }
    }
}

// ---------------- launch ----------------
extern "C" void kernel_launch(void* const* d_in, const int* in_sizes, int n_in,
                              void* d_out, int out_size)
{
    const float* x  = (const float*)d_in[0];
    const int*   ei = (const int*)d_in[1];     // int32 (JAX x64 disabled)
    const float* msgW1 = (const float*)d_in[2];
    const float* msgB1 = (const float*)d_in[3];
    const float* msgW2 = (const float*)d_in[4];
    const float* msgB2 = (const float*)d_in[5];
    const float* updW1 = (const float*)d_in[6];
    const float* updB1 = (const float*)d_in[7];
    const float* updW2 = (const float*)d_in[8];
    const float* updB2 = (const float*)d_in[9];
    const float* attW1 = (const float*)d_in[10];
    const float* attB1 = (const float*)d_in[11];
    const float* attW2 = (const float*)d_in[12];
    const float* attB2 = (const float*)d_in[13];
    const float* glbW  = (const float*)d_in[14];
    const float* glbB  = (const float*)d_in[15];

    int n = in_sizes[0] / D;
    int E = in_sizes[1] / 2;
    const int* src  = ei;
    const int* dstp = ei + E;
    float* out = (float*)d_out;

    float* h1 = nullptr;  float* zP = nullptr;  float* saP = nullptr;
    cudaGetSymbolAddress((void**)&h1,  g_h1);
    cudaGetSymbolAddress((void**)&zP,  g_z);
    cudaGetSymbolAddress((void**)&saP, g_satt);

    int eb = (E + TM - 1) / TM;
    int nb = (n + TM - 1) / TM;

    // fixed across steps
    mean1_kernel<<<NB_MEAN, 128>>>(x, n);
    repr_kernel<<<1, 128>>>(glbW, glbB, n);
    fuse_kernel<<<D, 128>>>(msgW2, msgB2, updW1);
    wconv_kernel<<<dim3(D, 7), D>>>(msgW1, attW1, updW1, updW2);

    // step 1: h = x
    pre_kernel<<<nb, 128>>>(x, n);
    cudaMemsetAsync(zP, 0, (size_t)n * D * sizeof(float));
    cudaMemsetAsync(saP, 0, (size_t)n * sizeof(float));
    edge_kernel<<<eb, 128>>>(src, dstp, msgB1, attB1, attW2, attB2, E, n);
    upd_kernel<<<nb, 128>>>(x, updB1, updB2, h1, n);

    // step 2: h = g_h1, output -> d_out
    pre_kernel<<<nb, 128>>>(h1, n);
    cudaMemsetAsync(zP, 0, (size_t)n * D * sizeof(float));
    cudaMemsetAsync(saP, 0, (size_t)n * sizeof(float));
    edge_kernel<<<eb, 128>>>(src, dstp, msgB1, attB1, attW2, attB2, E, n);
    upd_kernel<<<nb, 128>>>(h1, updB1, updB2, out, n);
}

// round 9
// speedup vs baseline: 9.7977x; 1.3343x over previous
#include <cuda_runtime.h>
#include <cuda_fp16.h>
#include <math.h>

#define D   128
#define TM  32
#define NMAX 50000
#define NB_MEAN 200

// ---- scratch (device globals: allocation-free) ----
__device__ float  g_h1[NMAX * D];      // h after step 1
__device__ __align__(16) float g_z[NMAX * D];   // scatter: sum att*relu(u)
__device__ float  g_satt[NMAX];        // scatter: sum att
// per node, 256 halves: interleaved pairs (Pt[j], At[j]) as __half2 at pair-index j
__device__ __align__(16) __half g_srcp[NMAX * 256];
// per node, interleaved pairs (Pb[j], Ab[j])
__device__ __align__(16) __half g_dstp[NMAX * 256];
__device__ float  g_Ht[NMAX * D];      // h @ updW1_top
__device__ float  g_M[D * D];          // msgW2 @ updW1_bot (fused, fp32)
__device__ float  g_bb[D];             // msgB2 @ updW1_bot
__device__ float  g_part[NB_MEAN * D];
__device__ float  g_repr[D];
// fp16 transposed weights, [n][k] row-major, 7 matrices:
// 0:msgW1top 1:attW1top 2:msgW1bot 3:attW1bot 4:updW1top 5:M 6:updW2
__device__ __align__(16) __half g_WT[7 * D * D];

__device__ __forceinline__ void red_add_v4(float* a, float4 v) {
    asm volatile("red.global.add.v4.f32 [%0], {%1,%2,%3,%4};"
                 :: "l"(a), "f"(v.x), "f"(v.y), "f"(v.z), "f"(v.w) : "memory");
}

__device__ __forceinline__ void mma16816(float* d, const unsigned* a,
                                         unsigned b0, unsigned b1) {
    asm volatile(
        "mma.sync.aligned.m16n8k16.row.col.f32.f16.f16.f32 "
        "{%0,%1,%2,%3}, {%4,%5,%6,%7}, {%8,%9}, {%0,%1,%2,%3};"
        : "+f"(d[0]), "+f"(d[1]), "+f"(d[2]), "+f"(d[3])
        : "r"(a[0]), "r"(a[1]), "r"(a[2]), "r"(a[3]), "r"(b0), "r"(b1));
}

// ---------------- small setup kernels ----------------
__global__ void mean1_kernel(const float* __restrict__ x, int n) {
    int b = blockIdx.x, j = threadIdx.x;
    int per = (n + NB_MEAN - 1) / NB_MEAN;
    int r0 = b * per;
    int r1 = r0 + per; if (r1 > n) r1 = n;
    float s = 0.f;
    for (int r = r0; r < r1; r++) s += x[(size_t)r * D + j];
    g_part[b * D + j] = s;
}

__global__ void repr_kernel(const float* __restrict__ glbW,
                            const float* __restrict__ glbB, int n) {
    __shared__ float meanS[D];
    int j = threadIdx.x;
    float s = 0.f;
    for (int b = 0; b < NB_MEAN; b++) s += g_part[b * D + j];
    meanS[j] = s / (float)n;
    __syncthreads();
    float a = glbB[j];
    #pragma unroll 4
    for (int k = 0; k < D; k++) a = fmaf(meanS[k], glbW[k * D + j], a);
    g_repr[j] = fmaxf(a, 0.f);
}

// M[k][j] = sum_t msgW2[k][t] * updW1_bot[t][j];  bb[j] = sum_t msgB2[t]*updW1_bot[t][j]
__global__ void fuse_kernel(const float* __restrict__ msgW2,
                            const float* __restrict__ msgB2,
                            const float* __restrict__ updW1) {
    int k = blockIdx.x, j = threadIdx.x;
    float s = 0.f;
    for (int t = 0; t < D; t++)
        s = fmaf(msgW2[k * D + t], updW1[(D + t) * D + j], s);
    g_M[k * D + j] = s;
    if (k == 0) {
        float b = 0.f;
        for (int t = 0; t < D; t++)
            b = fmaf(msgB2[t], updW1[(D + t) * D + j], b);
        g_bb[j] = b;
    }
}

// transpose + fp16-convert the 7 weight matrices into g_WT  (runs after fuse_kernel)
__global__ void wconv_kernel(const float* __restrict__ msgW1,
                             const float* __restrict__ attW1,
                             const float* __restrict__ updW1,
                             const float* __restrict__ updW2) {
    int nrow = blockIdx.x;   // output feature n
    int k    = threadIdx.x;  // reduction index k
    int m    = blockIdx.y;
    float v;
    switch (m) {
        case 0: v = msgW1[k * D + nrow]; break;
        case 1: v = attW1[k * D + nrow]; break;
        case 2: v = msgW1[(D + k) * D + nrow]; break;
        case 3: v = attW1[(D + k) * D + nrow]; break;
        case 4: v = updW1[k * D + nrow]; break;
        case 5: v = g_M[k * D + nrow]; break;
        default: v = updW2[k * D + nrow]; break;
    }
    g_WT[m * D * D + nrow * D + k] = __float2half(v);
}

// ---- warp-level fp16 MMA GEMM over a 32x128 tile (SRC fp16 smem, stride 136) ----
#define MMA_GEMM(ACC, WI, SRC) { \
    _Pragma("unroll") for (int mt_ = 0; mt_ < 2; mt_++) \
    _Pragma("unroll") for (int nt_ = 0; nt_ < 4; nt_++) \
    _Pragma("unroll") for (int e_ = 0; e_ < 4; e_++) ACC[mt_][nt_][e_] = 0.f; \
    const __half* WT_ = g_WT + (WI) * D * D; \
    _Pragma("unroll") \
    for (int kc = 0; kc < 8; kc++) { \
        unsigned a0[4], a1[4]; \
        a0[0] = *(const unsigned*)&SRC[g][16*kc + 2*t]; \
        a0[1] = *(const unsigned*)&SRC[g + 8][16*kc + 2*t]; \
        a0[2] = *(const unsigned*)&SRC[g][16*kc + 2*t + 8]; \
        a0[3] = *(const unsigned*)&SRC[g + 8][16*kc + 2*t + 8]; \
        a1[0] = *(const unsigned*)&SRC[16 + g][16*kc + 2*t]; \
        a1[1] = *(const unsigned*)&SRC[24 + g][16*kc + 2*t]; \
        a1[2] = *(const unsigned*)&SRC[16 + g][16*kc + 2*t + 8]; \
        a1[3] = *(const unsigned*)&SRC[24 + g][16*kc + 2*t + 8]; \
        _Pragma("unroll") \
        for (int nt = 0; nt < 4; nt++) { \
            int nrow_ = 32*w + 8*nt + g; \
            unsigned b0 = *(const unsigned*)&WT_[nrow_ * D + 16*kc + 2*t]; \
            unsigned b1 = *(const unsigned*)&WT_[nrow_ * D + 16*kc + 2*t + 8]; \
            mma16816(ACC[0][nt], a0, b0, b1); \
            mma16816(ACC[1][nt], a1, b0, b1); \
        } \
    } }

// ---------------- pre kernel: 5 GEMMs via tensor cores ----------------
__global__ __launch_bounds__(128, 4)
void pre_kernel(const float* __restrict__ h, int n)
{
    __shared__ __half hsf[TM][136];
    int tid = threadIdx.x, lane = tid & 31, w = tid >> 5;
    int g = lane >> 2, t = lane & 3;
    int n0 = blockIdx.x * TM;

    for (int i = tid; i < TM * 32; i += 128) {
        int m = i >> 5, q = i & 31;
        int node = n0 + m; if (node >= n) node = n - 1;
        float4 v = ((const float4*)(h + (size_t)node * D))[q];
        *(__half2*)&hsf[m][4*q]     = __floats2half2_rn(v.x, v.y);
        *(__half2*)&hsf[m][4*q + 2] = __floats2half2_rn(v.z, v.w);
    }
    __syncthreads();

    float accP[2][4][4], accA[2][4][4];

    #define STORE_ILV(OUT) \
        _Pragma("unroll") for (int mt = 0; mt < 2; mt++) \
        _Pragma("unroll") for (int nt = 0; nt < 4; nt++) { \
            int row = 16*mt + g, col = 32*w + 8*nt + 2*t; \
            int node = n0 + row; \
            if (node < n) { \
                __half2 p = __floats2half2_rn(accP[mt][nt][0], accP[mt][nt][1]); \
                __half2 a = __floats2half2_rn(accA[mt][nt][0], accA[mt][nt][1]); \
                __half2 o0 = __lows2half2(p, a), o1 = __highs2half2(p, a); \
                uint2 u; u.x = *(unsigned*)&o0; u.y = *(unsigned*)&o1; \
                *(uint2*)(OUT + (size_t)node * 256 + 2*col) = u; \
            } \
            int node2 = n0 + row + 8; \
            if (node2 < n) { \
                __half2 p = __floats2half2_rn(accP[mt][nt][2], accP[mt][nt][3]); \
                __half2 a = __floats2half2_rn(accA[mt][nt][2], accA[mt][nt][3]); \
                __half2 o0 = __lows2half2(p, a), o1 = __highs2half2(p, a); \
                uint2 u; u.x = *(unsigned*)&o0; u.y = *(unsigned*)&o1; \
                *(uint2*)(OUT + (size_t)node2 * 256 + 2*col) = u; \
            } \
        }

    MMA_GEMM(accP, 0, hsf)
    MMA_GEMM(accA, 1, hsf)
    STORE_ILV(g_srcp)
    MMA_GEMM(accP, 2, hsf)
    MMA_GEMM(accA, 3, hsf)
    STORE_ILV(g_dstp)
    #undef STORE_ILV

    MMA_GEMM(accP, 4, hsf)
    #pragma unroll
    for (int mt = 0; mt < 2; mt++)
    #pragma unroll
    for (int nt = 0; nt < 4; nt++) {
        int row = 16*mt + g, col = 32*w + 8*nt + 2*t;
        int node = n0 + row;
        if (node < n) {
            float2 v = make_float2(accP[mt][nt][0], accP[mt][nt][1]);
            *(float2*)&g_Ht[(size_t)node * D + col] = v;
        }
        int node2 = n0 + row + 8;
        if (node2 < n) {
            float2 v = make_float2(accP[mt][nt][2], accP[mt][nt][3]);
            *(float2*)&g_Ht[(size_t)node2 * D + col] = v;
        }
    }
}

// ---------------- edge kernel: vector gather, warp-local attention, reg scatter ----
// thread (mg=j>>5, q=j&31): edges mg*8..mg*8+7, cols 4q..4q+3 (one uint4 per row)
// warp w == mg -> att partial write / reduce / scatter are warp-local.
__global__ __launch_bounds__(128, 6)
void edge_kernel(const int* __restrict__ src, const int* __restrict__ dst,
                 const float* __restrict__ msgB1,
                 const float* __restrict__ attB1,
                 const float* __restrict__ attW2,
                 const float* __restrict__ attB2, int E, int n)
{
    __shared__ float ws[TM][D];   // attention partials
    __shared__ float att_s[TM];
    __shared__ int sS[TM], sD[TM];

    int j  = threadIdx.x;
    int e0 = blockIdx.x * TM;

    if (j < TM) {
        int e = e0 + j;
        int s = 0, d = 0;
        if (e < E) { s = src[e]; d = dst[e]; }
        if (s < 0) s = 0; if (s >= n) s = n - 1;
        if (d < 0) d = 0; if (d >= n) d = n - 1;
        sS[j] = s; sD[j] = d;
    }
    __syncthreads();

    int q = j & 31, mg = j >> 5, lane = j & 31;
    const uint4* SP = (const uint4*)g_srcp;   // 32 uint4 per node row
    const uint4* DP = (const uint4*)g_dstp;
    float4 b1 = *(const float4*)&msgB1[4*q];
    float4 a1 = *(const float4*)&attB1[4*q];
    float4 aw = *(const float4*)&attW2[4*q];

    float4 rr[8];
    #pragma unroll
    for (int r8 = 0; r8 < 8; r8++) {
        int m = mg * 8 + r8;
        uint4 su = SP[(size_t)sS[m] * 32 + q];
        uint4 du = DP[(size_t)sD[m] * 32 + q];
        float2 s0 = __half22float2(*(__half2*)&su.x), d0 = __half22float2(*(__half2*)&du.x);
        float2 s1 = __half22float2(*(__half2*)&su.y), d1 = __half22float2(*(__half2*)&du.y);
        float2 s2 = __half22float2(*(__half2*)&su.z), d2 = __half22float2(*(__half2*)&du.z);
        float2 s3 = __half22float2(*(__half2*)&su.w), d3 = __half22float2(*(__half2*)&du.w);
        rr[r8].x = fmaxf(s0.x + d0.x + b1.x, 0.f);
        rr[r8].y = fmaxf(s1.x + d1.x + b1.y, 0.f);
        rr[r8].z = fmaxf(s2.x + d2.x + b1.z, 0.f);
        rr[r8].w = fmaxf(s3.x + d3.x + b1.w, 0.f);
        float4 av;
        av.x = fmaxf(s0.y + d0.y + a1.x, 0.f) * aw.x;
        av.y = fmaxf(s1.y + d1.y + a1.y, 0.f) * aw.y;
        av.z = fmaxf(s2.y + d2.y + a1.z, 0.f) * aw.z;
        av.w = fmaxf(s3.y + d3.y + a1.w, 0.f) * aw.w;
        *(float4*)&ws[m][4*q] = av;
    }
    __syncwarp();

    // warp-local attention reduce over this warp's 8 edges
    {
        float ab2 = attB2[0];
        #pragma unroll
        for (int mm = 0; mm < 8; mm++) {
            int m = mg * 8 + mm;
            float s4 = ws[m][lane] + ws[m][lane + 32] + ws[m][lane + 64] + ws[m][lane + 96];
            #pragma unroll
            for (int off = 16; off > 0; off >>= 1)
                s4 += __shfl_xor_sync(0xffffffffu, s4, off);
            if (lane == 0) {
                float a = 1.f / (1.f + expf(-(s4 + ab2)));
                att_s[m] = a;
                if (e0 + m < E) atomicAdd(&g_satt[sD[m]], a);
            }
        }
    }
    __syncwarp();

    // scatter directly from registers
    #pragma unroll
    for (int r8 = 0; r8 < 8; r8++) {
        int m = mg * 8 + r8;
        if (e0 + m < E) {
            float a = att_s[m];
            float4 v = make_float4(rr[r8].x * a, rr[r8].y * a, rr[r8].z * a, rr[r8].w * a);
            red_add_v4(&g_z[(size_t)sD[m] * D + 4*q], v);
        }
    }
}

// ---------------- update kernel: 2 GEMMs via tensor cores ----------------
__global__ __launch_bounds__(128, 4)
void upd_kernel(const float* __restrict__ h,
                const float* __restrict__ updB1,
                const float* __restrict__ updB2,
                float* __restrict__ out, int n)
{
    __shared__ __half zsf[TM][136];
    __shared__ __half hid[TM][136];
    int tid = threadIdx.x, lane = tid & 31, w = tid >> 5;
    int g = lane >> 2, t = lane & 3;
    int n0 = blockIdx.x * TM;

    for (int i = tid; i < TM * 32; i += 128) {
        int m = i >> 5, q = i & 31;
        int node = n0 + m; if (node >= n) node = n - 1;
        float4 v = ((const float4*)(g_z + (size_t)node * D))[q];
        *(__half2*)&zsf[m][4*q]     = __floats2half2_rn(v.x, v.y);
        *(__half2*)&zsf[m][4*q + 2] = __floats2half2_rn(v.z, v.w);
    }
    __syncthreads();

    float acc[2][4][4];

    // phase A: hid = relu(z@M + Ht + satt*bb + b1)
    MMA_GEMM(acc, 5, zsf)
    #pragma unroll
    for (int mt = 0; mt < 2; mt++)
    #pragma unroll
    for (int nt = 0; nt < 4; nt++) {
        int row = 16*mt + g, col = 32*w + 8*nt + 2*t;
        float2 bb = *(const float2*)&g_bb[col];
        float2 b1 = *(const float2*)&updB1[col];
        {
            int node = n0 + row;
            int nc = node < n ? node : n - 1;
            float2 ht = *(const float2*)&g_Ht[(size_t)nc * D + col];
            float sa = g_satt[nc];
            float v0 = fmaxf(acc[mt][nt][0] + ht.x + sa * bb.x + b1.x, 0.f);
            float v1 = fmaxf(acc[mt][nt][1] + ht.y + sa * bb.y + b1.y, 0.f);
            *(__half2*)&hid[row][col] = __floats2half2_rn(v0, v1);
        }
        {
            int node = n0 + row + 8;
            int nc = node < n ? node : n - 1;
            float2 ht = *(const float2*)&g_Ht[(size_t)nc * D + col];
            float sa = g_satt[nc];
            float v0 = fmaxf(acc[mt][nt][2] + ht.x + sa * bb.x + b1.x, 0.f);
            float v1 = fmaxf(acc[mt][nt][3] + ht.y + sa * bb.y + b1.y, 0.f);
            *(__half2*)&hid[row + 8][col] = __floats2half2_rn(v0, v1);
        }
    }
    __syncthreads();

    // phase B: out = hid@updW2 + b2 + h + repr
    MMA_GEMM(acc, 6, hid)
    #pragma unroll
    for (int mt = 0; mt < 2; mt++)
    #pragma unroll
    for (int nt = 0; nt < 4; nt++) {
        int row = 16*mt + g, col = 32*w + 8*nt + 2*t;
        float2 b2 = *(const float2*)&updB2[col];
        float2 gr = *(const float2*)&g_repr[col];
        {
            int node = n0 + row;
            if (node < n) {
                float2 hv = *(const float2*)&h[(size_t)node * D + col];
                float2 o = make_float2(acc[mt][nt][0] + b2.x + hv.x + gr.x,
                                       acc[mt][nt][1] + b2.y + hv.y + gr.y);
                *(float2*)&out[(size_t)node * D + col] = o;
            }
        }
        {
            int node = n0 + row + 8;
            if (node < n) {
                float2 hv = *(const float2*)&h[(size_t)node * D + col];
                float2 o = make_float2(acc[mt][nt][2] + b2.x + hv.x + gr.x,
                                       acc[mt][nt][3] + b2.y + hv.y + gr.y);
                *(float2*)&out[(size_t)node * D + col] = o;
            }
        }
    }
}

// ---------------- launch ----------------
extern "C" void kernel_launch(void* const* d_in, const int* in_sizes, int n_in,
                              void* d_out, int out_size)
{
    const float* x  = (const float*)d_in[0];
    const int*   ei = (const int*)d_in[1];     // int32 (JAX x64 disabled)
    const float* msgW1 = (const float*)d_in[2];
    const float* msgB1 = (const float*)d_in[3];
    const float* msgW2 = (const float*)d_in[4];
    const float* msgB2 = (const float*)d_in[5];
    const float* updW1 = (const float*)d_in[6];
    const float* updB1 = (const float*)d_in[7];
    const float* updW2 = (const float*)d_in[8];
    const float* updB2 = (const float*)d_in[9];
    const float* attW1 = (const float*)d_in[10];
    const float* attB1 = (const float*)d_in[11];
    const float* attW2 = (const float*)d_in[12];
    const float* attB2 = (const float*)d_in[13];
    const float* glbW  = (const float*)d_in[14];
    const float* glbB  = (const float*)d_in[15];

    int n = in_sizes[0] / D;
    int E = in_sizes[1] / 2;
    const int* src  = ei;
    const int* dstp = ei + E;
    float* out = (float*)d_out;

    float* h1 = nullptr;  float* zP = nullptr;  float* saP = nullptr;
    cudaGetSymbolAddress((void**)&h1,  g_h1);
    cudaGetSymbolAddress((void**)&zP,  g_z);
    cudaGetSymbolAddress((void**)&saP, g_satt);

    int eb = (E + TM - 1) / TM;
    int nb = (n + TM - 1) / TM;

    // fixed across steps
    mean1_kernel<<<NB_MEAN, 128>>>(x, n);
    repr_kernel<<<1, 128>>>(glbW, glbB, n);
    fuse_kernel<<<D, 128>>>(msgW2, msgB2, updW1);
    wconv_kernel<<<dim3(D, 7), D>>>(msgW1, attW1, updW1, updW2);

    // step 1: h = x
    cudaMemsetAsync(zP, 0, (size_t)n * D * sizeof(float));
    cudaMemsetAsync(saP, 0, (size_t)n * sizeof(float));
    pre_kernel<<<nb, 128>>>(x, n);
    edge_kernel<<<eb, 128>>>(src, dstp, msgB1, attB1, attW2, attB2, E, n);
    upd_kernel<<<nb, 128>>>(x, updB1, updB2, h1, n);

    // step 2: h = g_h1, output -> d_out
    cudaMemsetAsync(zP, 0, (size_t)n * D * sizeof(float));
    cudaMemsetAsync(saP, 0, (size_t)n * sizeof(float));
    pre_kernel<<<nb, 128>>>(h1, n);
    edge_kernel<<<eb, 128>>>(src, dstp, msgB1, attB1, attW2, attB2, E, n);
    upd_kernel<<<nb, 128>>>(h1, updB1, updB2, out, n);
}

// round 10
// speedup vs baseline: 11.7731x; 1.2016x over previous
#include <cuda_runtime.h>
#include <cuda_fp16.h>
#include <math.h>

#define D   128
#define TM  32
#define NMAX 50000
#define NB_MEAN 200

// ---- scratch (device globals: allocation-free) ----
__device__ float  g_h1[NMAX * D];      // h after step 1
__device__ __align__(16) float g_z[NMAX * D];   // scatter: sum att*relu(u)
__device__ float  g_satt[NMAX];        // scatter: sum att
// per node, 256 halves: interleaved pairs (Pt[j], At[j]) as __half2 at pair-index j
__device__ __align__(16) __half g_srcp[NMAX * 256];
// per node, interleaved pairs (Pb[j], Ab[j])
__device__ __align__(16) __half g_dstp[NMAX * 256];
__device__ float  g_Ht[NMAX * D];      // h @ updW1_top
__device__ float  g_M[D * D];          // msgW2 @ updW1_bot (fused, fp32)
__device__ float  g_bb[D];             // msgB2 @ updW1_bot
__device__ float  g_part[NB_MEAN * D];
__device__ float  g_repr[D];
// fp16 transposed weights, [n][k] row-major, 7 matrices:
// 0:msgW1top 1:attW1top 2:msgW1bot 3:attW1bot 4:updW1top 5:M 6:updW2
__device__ __align__(16) __half g_WT[7 * D * D];

__device__ __forceinline__ void red_add_v4(float* a, float4 v) {
    asm volatile("red.global.add.v4.f32 [%0], {%1,%2,%3,%4};"
                 :: "l"(a), "f"(v.x), "f"(v.y), "f"(v.z), "f"(v.w) : "memory");
}

__device__ __forceinline__ void mma16816(float* d, const unsigned* a,
                                         unsigned b0, unsigned b1) {
    asm volatile(
        "mma.sync.aligned.m16n8k16.row.col.f32.f16.f16.f32 "
        "{%0,%1,%2,%3}, {%4,%5,%6,%7}, {%8,%9}, {%0,%1,%2,%3};"
        : "+f"(d[0]), "+f"(d[1]), "+f"(d[2]), "+f"(d[3])
        : "r"(a[0]), "r"(a[1]), "r"(a[2]), "r"(a[3]), "r"(b0), "r"(b1));
}

// ---------------- small setup kernels ----------------
__global__ void mean1_kernel(const float* __restrict__ x, int n) {
    int b = blockIdx.x, j = threadIdx.x;
    int per = (n + NB_MEAN - 1) / NB_MEAN;
    int r0 = b * per;
    int r1 = r0 + per; if (r1 > n) r1 = n;
    float s = 0.f;
    for (int r = r0; r < r1; r++) s += x[(size_t)r * D + j];
    g_part[b * D + j] = s;
}

__global__ void repr_kernel(const float* __restrict__ glbW,
                            const float* __restrict__ glbB, int n) {
    __shared__ float meanS[D];
    int j = threadIdx.x;
    float s = 0.f;
    for (int b = 0; b < NB_MEAN; b++) s += g_part[b * D + j];
    meanS[j] = s / (float)n;
    __syncthreads();
    float a = glbB[j];
    #pragma unroll 4
    for (int k = 0; k < D; k++) a = fmaf(meanS[k], glbW[k * D + j], a);
    g_repr[j] = fmaxf(a, 0.f);
}

// M[k][j] = sum_t msgW2[k][t] * updW1_bot[t][j];  bb[j] = sum_t msgB2[t]*updW1_bot[t][j]
__global__ void fuse_kernel(const float* __restrict__ msgW2,
                            const float* __restrict__ msgB2,
                            const float* __restrict__ updW1) {
    int k = blockIdx.x, j = threadIdx.x;
    float s = 0.f;
    for (int t = 0; t < D; t++)
        s = fmaf(msgW2[k * D + t], updW1[(D + t) * D + j], s);
    g_M[k * D + j] = s;
    if (k == 0) {
        float b = 0.f;
        for (int t = 0; t < D; t++)
            b = fmaf(msgB2[t], updW1[(D + t) * D + j], b);
        g_bb[j] = b;
    }
}

// transpose + fp16-convert the 7 weight matrices into g_WT  (runs after fuse_kernel)
__global__ void wconv_kernel(const float* __restrict__ msgW1,
                             const float* __restrict__ attW1,
                             const float* __restrict__ updW1,
                             const float* __restrict__ updW2) {
    int nrow = blockIdx.x;   // output feature n
    int k    = threadIdx.x;  // reduction index k
    int m    = blockIdx.y;
    float v;
    switch (m) {
        case 0: v = msgW1[k * D + nrow]; break;
        case 1: v = attW1[k * D + nrow]; break;
        case 2: v = msgW1[(D + k) * D + nrow]; break;
        case 3: v = attW1[(D + k) * D + nrow]; break;
        case 4: v = updW1[k * D + nrow]; break;
        case 5: v = g_M[k * D + nrow]; break;
        default: v = updW2[k * D + nrow]; break;
    }
    g_WT[m * D * D + nrow * D + k] = __float2half(v);
}

// ---- warp-level fp16 MMA GEMM over a 32x128 tile (SRC fp16 smem, stride 136) ----
#define MMA_GEMM(ACC, WI, SRC) { \
    _Pragma("unroll") for (int mt_ = 0; mt_ < 2; mt_++) \
    _Pragma("unroll") for (int nt_ = 0; nt_ < 4; nt_++) \
    _Pragma("unroll") for (int e_ = 0; e_ < 4; e_++) ACC[mt_][nt_][e_] = 0.f; \
    const __half* WT_ = g_WT + (WI) * D * D; \
    _Pragma("unroll") \
    for (int kc = 0; kc < 8; kc++) { \
        unsigned a0[4], a1[4]; \
        a0[0] = *(const unsigned*)&SRC[g][16*kc + 2*t]; \
        a0[1] = *(const unsigned*)&SRC[g + 8][16*kc + 2*t]; \
        a0[2] = *(const unsigned*)&SRC[g][16*kc + 2*t + 8]; \
        a0[3] = *(const unsigned*)&SRC[g + 8][16*kc + 2*t + 8]; \
        a1[0] = *(const unsigned*)&SRC[16 + g][16*kc + 2*t]; \
        a1[1] = *(const unsigned*)&SRC[24 + g][16*kc + 2*t]; \
        a1[2] = *(const unsigned*)&SRC[16 + g][16*kc + 2*t + 8]; \
        a1[3] = *(const unsigned*)&SRC[24 + g][16*kc + 2*t + 8]; \
        _Pragma("unroll") \
        for (int nt = 0; nt < 4; nt++) { \
            int nrow_ = 32*w + 8*nt + g; \
            unsigned b0 = *(const unsigned*)&WT_[nrow_ * D + 16*kc + 2*t]; \
            unsigned b1 = *(const unsigned*)&WT_[nrow_ * D + 16*kc + 2*t + 8]; \
            mma16816(ACC[0][nt], a0, b0, b1); \
            mma16816(ACC[1][nt], a1, b0, b1); \
        } \
    } }

// ---------------- pre kernel: 5 GEMMs via tensor cores ----------------
__global__ __launch_bounds__(128, 4)
void pre_kernel(const float* __restrict__ h, int n)
{
    __shared__ __half hsf[TM][136];
    int tid = threadIdx.x, lane = tid & 31, w = tid >> 5;
    int g = lane >> 2, t = lane & 3;
    int n0 = blockIdx.x * TM;

    for (int i = tid; i < TM * 32; i += 128) {
        int m = i >> 5, q = i & 31;
        int node = n0 + m; if (node >= n) node = n - 1;
        float4 v = ((const float4*)(h + (size_t)node * D))[q];
        *(__half2*)&hsf[m][4*q]     = __floats2half2_rn(v.x, v.y);
        *(__half2*)&hsf[m][4*q + 2] = __floats2half2_rn(v.z, v.w);
    }
    __syncthreads();

    float accP[2][4][4], accA[2][4][4];

    #define STORE_ILV(OUT) \
        _Pragma("unroll") for (int mt = 0; mt < 2; mt++) \
        _Pragma("unroll") for (int nt = 0; nt < 4; nt++) { \
            int row = 16*mt + g, col = 32*w + 8*nt + 2*t; \
            int node = n0 + row; \
            if (node < n) { \
                __half2 p = __floats2half2_rn(accP[mt][nt][0], accP[mt][nt][1]); \
                __half2 a = __floats2half2_rn(accA[mt][nt][0], accA[mt][nt][1]); \
                __half2 o0 = __lows2half2(p, a), o1 = __highs2half2(p, a); \
                uint2 u; u.x = *(unsigned*)&o0; u.y = *(unsigned*)&o1; \
                *(uint2*)(OUT + (size_t)node * 256 + 2*col) = u; \
            } \
            int node2 = n0 + row + 8; \
            if (node2 < n) { \
                __half2 p = __floats2half2_rn(accP[mt][nt][2], accP[mt][nt][3]); \
                __half2 a = __floats2half2_rn(accA[mt][nt][2], accA[mt][nt][3]); \
                __half2 o0 = __lows2half2(p, a), o1 = __highs2half2(p, a); \
                uint2 u; u.x = *(unsigned*)&o0; u.y = *(unsigned*)&o1; \
                *(uint2*)(OUT + (size_t)node2 * 256 + 2*col) = u; \
            } \
        }

    MMA_GEMM(accP, 0, hsf)
    MMA_GEMM(accA, 1, hsf)
    STORE_ILV(g_srcp)
    MMA_GEMM(accP, 2, hsf)
    MMA_GEMM(accA, 3, hsf)
    STORE_ILV(g_dstp)
    #undef STORE_ILV

    MMA_GEMM(accP, 4, hsf)
    #pragma unroll
    for (int mt = 0; mt < 2; mt++)
    #pragma unroll
    for (int nt = 0; nt < 4; nt++) {
        int row = 16*mt + g, col = 32*w + 8*nt + 2*t;
        int node = n0 + row;
        if (node < n) {
            float2 v = make_float2(accP[mt][nt][0], accP[mt][nt][1]);
            *(float2*)&g_Ht[(size_t)node * D + col] = v;
        }
        int node2 = n0 + row + 8;
        if (node2 < n) {
            float2 v = make_float2(accP[mt][nt][2], accP[mt][nt][3]);
            *(float2*)&g_Ht[(size_t)node2 * D + col] = v;
        }
    }
}

// ---------------- edge kernel: warp-autonomous, zero smem ----------------
// Warp = 8 edges. Lane q covers cols 4q..4q+3 of each edge.
// Indices broadcast via shfl; att dot = shfl_xor reduce; scatter from regs.
__global__ __launch_bounds__(128, 8)
void edge_kernel(const int* __restrict__ src, const int* __restrict__ dst,
                 const float* __restrict__ msgB1,
                 const float* __restrict__ attB1,
                 const float* __restrict__ attW2,
                 const float* __restrict__ attB2, int E, int n)
{
    int j    = threadIdx.x;
    int lane = j & 31, mg = j >> 5;
    int e0   = blockIdx.x * TM + mg * 8;   // this warp's first edge
    int q    = lane;

    // per-lane index load for edge e0 + (lane&7)  (4x redundant across warp; L1-hit)
    int eL = e0 + (lane & 7);
    int sL = 0, dL = 0;
    if (eL < E) { sL = src[eL]; dL = dst[eL]; }
    if (sL < 0) sL = 0; if (sL >= n) sL = n - 1;
    if (dL < 0) dL = 0; if (dL >= n) dL = n - 1;

    const uint4* SP = (const uint4*)g_srcp;   // 32 uint4 per node row
    const uint4* DP = (const uint4*)g_dstp;
    float4 b1 = *(const float4*)&msgB1[4*q];
    float4 a1 = *(const float4*)&attB1[4*q];
    float4 aw = *(const float4*)&attW2[4*q];
    float ab2 = attB2[0];

    // broadcast the 8 (src,dst) pairs
    int sA[8], dA[8];
    #pragma unroll
    for (int r8 = 0; r8 < 8; r8++) {
        sA[r8] = __shfl_sync(0xffffffffu, sL, r8);
        dA[r8] = __shfl_sync(0xffffffffu, dL, r8);
    }

    #pragma unroll
    for (int r8 = 0; r8 < 8; r8++) {
        uint4 su = SP[(size_t)sA[r8] * 32 + q];
        uint4 du = DP[(size_t)dA[r8] * 32 + q];
        float2 s0 = __half22float2(*(__half2*)&su.x), d0 = __half22float2(*(__half2*)&du.x);
        float2 s1 = __half22float2(*(__half2*)&su.y), d1 = __half22float2(*(__half2*)&du.y);
        float2 s2 = __half22float2(*(__half2*)&su.z), d2 = __half22float2(*(__half2*)&du.z);
        float2 s3 = __half22float2(*(__half2*)&su.w), d3 = __half22float2(*(__half2*)&du.w);

        float4 rr;
        rr.x = fmaxf(s0.x + d0.x + b1.x, 0.f);
        rr.y = fmaxf(s1.x + d1.x + b1.y, 0.f);
        rr.z = fmaxf(s2.x + d2.x + b1.z, 0.f);
        rr.w = fmaxf(s3.x + d3.x + b1.w, 0.f);

        float pa = fmaf(fmaxf(s0.y + d0.y + a1.x, 0.f), aw.x,
                   fmaf(fmaxf(s1.y + d1.y + a1.y, 0.f), aw.y,
                   fmaf(fmaxf(s2.y + d2.y + a1.z, 0.f), aw.z,
                        fmaxf(s3.y + d3.y + a1.w, 0.f) * aw.w)));
        #pragma unroll
        for (int off = 16; off > 0; off >>= 1)
            pa += __shfl_xor_sync(0xffffffffu, pa, off);

        float a = 1.f / (1.f + expf(-(pa + ab2)));

        if (e0 + r8 < E) {
            float4 v = make_float4(rr.x * a, rr.y * a, rr.z * a, rr.w * a);
            red_add_v4(&g_z[(size_t)dA[r8] * D + 4*q], v);
            if (lane == 0) atomicAdd(&g_satt[dA[r8]], a);
        }
    }
}

// ---------------- update kernel: 2 GEMMs via tensor cores ----------------
__global__ __launch_bounds__(128, 4)
void upd_kernel(const float* __restrict__ h,
                const float* __restrict__ updB1,
                const float* __restrict__ updB2,
                float* __restrict__ out, int n)
{
    __shared__ __half zsf[TM][136];
    __shared__ __half hid[TM][136];
    int tid = threadIdx.x, lane = tid & 31, w = tid >> 5;
    int g = lane >> 2, t = lane & 3;
    int n0 = blockIdx.x * TM;

    for (int i = tid; i < TM * 32; i += 128) {
        int m = i >> 5, q = i & 31;
        int node = n0 + m; if (node >= n) node = n - 1;
        float4 v = ((const float4*)(g_z + (size_t)node * D))[q];
        *(__half2*)&zsf[m][4*q]     = __floats2half2_rn(v.x, v.y);
        *(__half2*)&zsf[m][4*q + 2] = __floats2half2_rn(v.z, v.w);
    }
    __syncthreads();

    float acc[2][4][4];

    // phase A: hid = relu(z@M + Ht + satt*bb + b1)
    MMA_GEMM(acc, 5, zsf)
    #pragma unroll
    for (int mt = 0; mt < 2; mt++)
    #pragma unroll
    for (int nt = 0; nt < 4; nt++) {
        int row = 16*mt + g, col = 32*w + 8*nt + 2*t;
        float2 bb = *(const float2*)&g_bb[col];
        float2 b1 = *(const float2*)&updB1[col];
        {
            int node = n0 + row;
            int nc = node < n ? node : n - 1;
            float2 ht = *(const float2*)&g_Ht[(size_t)nc * D + col];
            float sa = g_satt[nc];
            float v0 = fmaxf(acc[mt][nt][0] + ht.x + sa * bb.x + b1.x, 0.f);
            float v1 = fmaxf(acc[mt][nt][1] + ht.y + sa * bb.y + b1.y, 0.f);
            *(__half2*)&hid[row][col] = __floats2half2_rn(v0, v1);
        }
        {
            int node = n0 + row + 8;
            int nc = node < n ? node : n - 1;
            float2 ht = *(const float2*)&g_Ht[(size_t)nc * D + col];
            float sa = g_satt[nc];
            float v0 = fmaxf(acc[mt][nt][2] + ht.x + sa * bb.x + b1.x, 0.f);
            float v1 = fmaxf(acc[mt][nt][3] + ht.y + sa * bb.y + b1.y, 0.f);
            *(__half2*)&hid[row + 8][col] = __floats2half2_rn(v0, v1);
        }
    }
    __syncthreads();

    // phase B: out = hid@updW2 + b2 + h + repr
    MMA_GEMM(acc, 6, hid)
    #pragma unroll
    for (int mt = 0; mt < 2; mt++)
    #pragma unroll
    for (int nt = 0; nt < 4; nt++) {
        int row = 16*mt + g, col = 32*w + 8*nt + 2*t;
        float2 b2 = *(const float2*)&updB2[col];
        float2 gr = *(const float2*)&g_repr[col];
        {
            int node = n0 + row;
            if (node < n) {
                float2 hv = *(const float2*)&h[(size_t)node * D + col];
                float2 o = make_float2(acc[mt][nt][0] + b2.x + hv.x + gr.x,
                                       acc[mt][nt][1] + b2.y + hv.y + gr.y);
                *(float2*)&out[(size_t)node * D + col] = o;
            }
        }
        {
            int node = n0 + row + 8;
            if (node < n) {
                float2 hv = *(const float2*)&h[(size_t)node * D + col];
                float2 o = make_float2(acc[mt][nt][2] + b2.x + hv.x + gr.x,
                                       acc[mt][nt][3] + b2.y + hv.y + gr.y);
                *(float2*)&out[(size_t)node * D + col] = o;
            }
        }
    }
}

// ---------------- launch ----------------
extern "C" void kernel_launch(void* const* d_in, const int* in_sizes, int n_in,
                              void* d_out, int out_size)
{
    const float* x  = (const float*)d_in[0];
    const int*   ei = (const int*)d_in[1];     // int32 (JAX x64 disabled)
    const float* msgW1 = (const float*)d_in[2];
    const float* msgB1 = (const float*)d_in[3];
    const float* msgW2 = (const float*)d_in[4];
    const float* msgB2 = (const float*)d_in[5];
    const float* updW1 = (const float*)d_in[6];
    const float* updB1 = (const float*)d_in[7];
    const float* updW2 = (const float*)d_in[8];
    const float* updB2 = (const float*)d_in[9];
    const float* attW1 = (const float*)d_in[10];
    const float* attB1 = (const float*)d_in[11];
    const float* attW2 = (const float*)d_in[12];
    const float* attB2 = (const float*)d_in[13];
    const float* glbW  = (const float*)d_in[14];
    const float* glbB  = (const float*)d_in[15];

    int n = in_sizes[0] / D;
    int E = in_sizes[1] / 2;
    const int* src  = ei;
    const int* dstp = ei + E;
    float* out = (float*)d_out;

    float* h1 = nullptr;  float* zP = nullptr;  float* saP = nullptr;
    cudaGetSymbolAddress((void**)&h1,  g_h1);
    cudaGetSymbolAddress((void**)&zP,  g_z);
    cudaGetSymbolAddress((void**)&saP, g_satt);

    int eb = (E + TM - 1) / TM;
    int nb = (n + TM - 1) / TM;

    // fixed across steps
    mean1_kernel<<<NB_MEAN, 128>>>(x, n);
    repr_kernel<<<1, 128>>>(glbW, glbB, n);
    fuse_kernel<<<D, 128>>>(msgW2, msgB2, updW1);
    wconv_kernel<<<dim3(D, 7), D>>>(msgW1, attW1, updW1, updW2);

    // step 1: h = x
    cudaMemsetAsync(zP, 0, (size_t)n * D * sizeof(float));
    cudaMemsetAsync(saP, 0, (size_t)n * sizeof(float));
    pre_kernel<<<nb, 128>>>(x, n);
    edge_kernel<<<eb, 128>>>(src, dstp, msgB1, attB1, attW2, attB2, E, n);
    upd_kernel<<<nb, 128>>>(x, updB1, updB2, h1, n);

    // step 2: h = g_h1, output -> d_out
    cudaMemsetAsync(zP, 0, (size_t)n * D * sizeof(float));
    cudaMemsetAsync(saP, 0, (size_t)n * sizeof(float));
    pre_kernel<<<nb, 128>>>(h1, n);
    edge_kernel<<<eb, 128>>>(src, dstp, msgB1, attB1, attW2, attB2, E, n);
    upd_kernel<<<nb, 128>>>(h1, updB1, updB2, out, n);
}

// round 12
// speedup vs baseline: 13.9904x; 1.1883x over previous
#include <cuda_runtime.h>
#include <cuda_fp16.h>
#include <stdint.h>
#include <math.h>

#define D   128
#define TM  32
#define NMAX 50000
#define NB_MEAN 200

// ---- scratch (device globals: allocation-free) ----
__device__ float  g_h1[NMAX * D];      // h after step 1
__device__ __align__(16) float g_z[NMAX * D];   // scatter: sum att*relu(u)
__device__ float  g_satt[NMAX];        // scatter: sum att
// per node, 256 halves: interleaved pairs (Pt[j], At[j]) as __half2 at pair-index j
__device__ __align__(16) __half g_srcp[NMAX * 256];
// per node, interleaved pairs (Pb[j], Ab[j])
__device__ __align__(16) __half g_dstp[NMAX * 256];
__device__ float  g_Ht[NMAX * D];      // h @ updW1_top
__device__ float  g_M[D * D];          // msgW2 @ updW1_bot (fused, fp32)
__device__ float  g_bb[D];             // msgB2 @ updW1_bot
__device__ float  g_part[NB_MEAN * D];
__device__ float  g_repr[D];
// fp16 weights in MMA-B pair-packed layout:
// uint2{b0,b1} at index ((WI*128 + nrow)*8 + kc)*4 + t
// b0 = halves (16kc+2t, 16kc+2t+1), b1 = (+8, +9) of W^T[nrow][*]
// WI: 0:msgW1top 1:attW1top 2:msgW1bot 3:attW1bot 4:updW1top 5:M 6:updW2
__device__ __align__(16) uint2 g_WT[7 * D * 32];

__device__ __forceinline__ void red_add_v4(float* a, float4 v) {
    asm volatile("red.global.add.v4.f32 [%0], {%1,%2,%3,%4};"
                 :: "l"(a), "f"(v.x), "f"(v.y), "f"(v.z), "f"(v.w) : "memory");
}

__device__ __forceinline__ void mma16816(float* d, const unsigned* a,
                                         unsigned b0, unsigned b1) {
    asm volatile(
        "mma.sync.aligned.m16n8k16.row.col.f32.f16.f16.f32 "
        "{%0,%1,%2,%3}, {%4,%5,%6,%7}, {%8,%9}, {%0,%1,%2,%3};"
        : "+f"(d[0]), "+f"(d[1]), "+f"(d[2]), "+f"(d[3])
        : "r"(a[0]), "r"(a[1]), "r"(a[2]), "r"(a[3]), "r"(b0), "r"(b1));
}

__device__ __forceinline__ void ldsm_x4(unsigned* r, unsigned addr) {
    asm volatile("ldmatrix.sync.aligned.m8n8.x4.shared.b16 {%0,%1,%2,%3}, [%4];"
                 : "=r"(r[0]), "=r"(r[1]), "=r"(r[2]), "=r"(r[3]) : "r"(addr));
}

// ---------------- small setup kernels ----------------
__global__ void mean1_kernel(const float* __restrict__ x, int n) {
    int b = blockIdx.x, j = threadIdx.x;
    int per = (n + NB_MEAN - 1) / NB_MEAN;
    int r0 = b * per;
    int r1 = r0 + per; if (r1 > n) r1 = n;
    float s = 0.f;
    for (int r = r0; r < r1; r++) s += x[(size_t)r * D + j];
    g_part[b * D + j] = s;
}

__global__ void repr_kernel(const float* __restrict__ glbW,
                            const float* __restrict__ glbB, int n) {
    __shared__ float meanS[D];
    int j = threadIdx.x;
    float s = 0.f;
    for (int b = 0; b < NB_MEAN; b++) s += g_part[b * D + j];
    meanS[j] = s / (float)n;
    __syncthreads();
    float a = glbB[j];
    #pragma unroll 4
    for (int k = 0; k < D; k++) a = fmaf(meanS[k], glbW[k * D + j], a);
    g_repr[j] = fmaxf(a, 0.f);
}

// M[k][j] = sum_t msgW2[k][t] * updW1_bot[t][j];  bb[j] = sum_t msgB2[t]*updW1_bot[t][j]
__global__ void fuse_kernel(const float* __restrict__ msgW2,
                            const float* __restrict__ msgB2,
                            const float* __restrict__ updW1) {
    int k = blockIdx.x, j = threadIdx.x;
    float s = 0.f;
    for (int t = 0; t < D; t++)
        s = fmaf(msgW2[k * D + t], updW1[(D + t) * D + j], s);
    g_M[k * D + j] = s;
    if (k == 0) {
        float b = 0.f;
        for (int t = 0; t < D; t++)
            b = fmaf(msgB2[t], updW1[(D + t) * D + j], b);
        g_bb[j] = b;
    }
}

// convert 7 weight matrices into MMA-B pair-packed fp16 layout (after fuse_kernel)
// block = 32 threads: kc = tid>>2, t = tid&3 ; grid = (D, 7)
__global__ void wconv_kernel(const float* __restrict__ msgW1,
                             const float* __restrict__ attW1,
                             const float* __restrict__ updW1,
                             const float* __restrict__ updW2) {
    int nrow = blockIdx.x;
    int m    = blockIdx.y;
    int kc = threadIdx.x >> 2, t = threadIdx.x & 3;

    const float* W; int roff = 0;
    switch (m) {
        case 0: W = msgW1; break;
        case 1: W = attW1; break;
        case 2: W = msgW1; roff = D; break;
        case 3: W = attW1; roff = D; break;
        case 4: W = updW1; break;
        case 5: W = g_M;   break;
        default: W = updW2; break;
    }
    int k0 = 16 * kc + 2 * t;
    __half2 h0 = __floats2half2_rn(W[(roff + k0    ) * D + nrow], W[(roff + k0 + 1) * D + nrow]);
    __half2 h1 = __floats2half2_rn(W[(roff + k0 + 8) * D + nrow], W[(roff + k0 + 9) * D + nrow]);
    uint2 u; u.x = *(unsigned*)&h0; u.y = *(unsigned*)&h1;
    g_WT[((m * D + nrow) * 8 + kc) * 4 + t] = u;
}

// ---- warp-level fp16 MMA GEMM over a 32x128 tile (SRC fp16 smem, stride 136) ----
// A via ldmatrix.x4 (addr: row lane&15 [+16], col 16kc + 8*(lane>>4))
// B via pair-packed LDG.64
#define MMA_GEMM(ACC, WI, SRC) { \
    _Pragma("unroll") for (int mt_ = 0; mt_ < 2; mt_++) \
    _Pragma("unroll") for (int nt_ = 0; nt_ < 4; nt_++) \
    _Pragma("unroll") for (int e_ = 0; e_ < 4; e_++) ACC[mt_][nt_][e_] = 0.f; \
    const uint2* WT_ = g_WT + (WI) * D * 32; \
    unsigned aoff0 = (unsigned)__cvta_generic_to_shared(&SRC[lane & 15][8 * (lane >> 4)]); \
    unsigned aoff1 = (unsigned)__cvta_generic_to_shared(&SRC[16 + (lane & 15)][8 * (lane >> 4)]); \
    _Pragma("unroll") \
    for (int kc = 0; kc < 8; kc++) { \
        unsigned a0[4], a1[4]; \
        ldsm_x4(a0, aoff0 + 32 * kc); \
        ldsm_x4(a1, aoff1 + 32 * kc); \
        _Pragma("unroll") \
        for (int nt = 0; nt < 4; nt++) { \
            int nrow_ = 32 * w + 8 * nt + g; \
            uint2 b = WT_[(nrow_ * 8 + kc) * 4 + t]; \
            mma16816(ACC[0][nt], a0, b.x, b.y); \
            mma16816(ACC[1][nt], a1, b.x, b.y); \
        } \
    } }

// ---------------- pre kernel: 5 GEMMs via tensor cores ----------------
__global__ __launch_bounds__(128, 4)
void pre_kernel(const float* __restrict__ h, int n)
{
    __shared__ __half hsf[TM][136];
    int tid = threadIdx.x, lane = tid & 31, w = tid >> 5;
    int g = lane >> 2, t = lane & 3;
    int n0 = blockIdx.x * TM;

    for (int i = tid; i < TM * 32; i += 128) {
        int m = i >> 5, q = i & 31;
        int node = n0 + m; if (node >= n) node = n - 1;
        float4 v = ((const float4*)(h + (size_t)node * D))[q];
        *(__half2*)&hsf[m][4*q]     = __floats2half2_rn(v.x, v.y);
        *(__half2*)&hsf[m][4*q + 2] = __floats2half2_rn(v.z, v.w);
    }
    __syncthreads();

    float accP[2][4][4], accA[2][4][4];

    #define STORE_ILV(OUT) \
        _Pragma("unroll") for (int mt = 0; mt < 2; mt++) \
        _Pragma("unroll") for (int nt = 0; nt < 4; nt++) { \
            int row = 16*mt + g, col = 32*w + 8*nt + 2*t; \
            int node = n0 + row; \
            if (node < n) { \
                __half2 p = __floats2half2_rn(accP[mt][nt][0], accP[mt][nt][1]); \
                __half2 a = __floats2half2_rn(accA[mt][nt][0], accA[mt][nt][1]); \
                __half2 o0 = __lows2half2(p, a), o1 = __highs2half2(p, a); \
                uint2 u; u.x = *(unsigned*)&o0; u.y = *(unsigned*)&o1; \
                *(uint2*)(OUT + (size_t)node * 256 + 2*col) = u; \
            } \
            int node2 = n0 + row + 8; \
            if (node2 < n) { \
                __half2 p = __floats2half2_rn(accP[mt][nt][2], accP[mt][nt][3]); \
                __half2 a = __floats2half2_rn(accA[mt][nt][2], accA[mt][nt][3]); \
                __half2 o0 = __lows2half2(p, a), o1 = __highs2half2(p, a); \
                uint2 u; u.x = *(unsigned*)&o0; u.y = *(unsigned*)&o1; \
                *(uint2*)(OUT + (size_t)node2 * 256 + 2*col) = u; \
            } \
        }

    MMA_GEMM(accP, 0, hsf)
    MMA_GEMM(accA, 1, hsf)
    STORE_ILV(g_srcp)
    MMA_GEMM(accP, 2, hsf)
    MMA_GEMM(accA, 3, hsf)
    STORE_ILV(g_dstp)
    #undef STORE_ILV

    MMA_GEMM(accP, 4, hsf)
    #pragma unroll
    for (int mt = 0; mt < 2; mt++)
    #pragma unroll
    for (int nt = 0; nt < 4; nt++) {
        int row = 16*mt + g, col = 32*w + 8*nt + 2*t;
        int node = n0 + row;
        if (node < n) {
            float2 v = make_float2(accP[mt][nt][0], accP[mt][nt][1]);
            *(float2*)&g_Ht[(size_t)node * D + col] = v;
        }
        int node2 = n0 + row + 8;
        if (node2 < n) {
            float2 v = make_float2(accP[mt][nt][2], accP[mt][nt][3]);
            *(float2*)&g_Ht[(size_t)node2 * D + col] = v;
        }
    }
}

// ---------------- edge kernel: warp-autonomous, zero smem ----------------
__global__ __launch_bounds__(128, 8)
void edge_kernel(const int* __restrict__ src, const int* __restrict__ dst,
                 const float* __restrict__ msgB1,
                 const float* __restrict__ attB1,
                 const float* __restrict__ attW2,
                 const float* __restrict__ attB2, int E, int n)
{
    int j    = threadIdx.x;
    int lane = j & 31, mg = j >> 5;
    int e0   = blockIdx.x * TM + mg * 8;
    int q    = lane;

    int eL = e0 + (lane & 7);
    int sL = 0, dL = 0;
    if (eL < E) { sL = src[eL]; dL = dst[eL]; }
    if (sL < 0) sL = 0; if (sL >= n) sL = n - 1;
    if (dL < 0) dL = 0; if (dL >= n) dL = n - 1;

    const uint4* SP = (const uint4*)g_srcp;
    const uint4* DP = (const uint4*)g_dstp;
    float4 b1 = *(const float4*)&msgB1[4*q];
    float4 a1 = *(const float4*)&attB1[4*q];
    float4 aw = *(const float4*)&attW2[4*q];
    float ab2 = attB2[0];

    int sA[8], dA[8];
    #pragma unroll
    for (int r8 = 0; r8 < 8; r8++) {
        sA[r8] = __shfl_sync(0xffffffffu, sL, r8);
        dA[r8] = __shfl_sync(0xffffffffu, dL, r8);
    }

    #pragma unroll
    for (int r8 = 0; r8 < 8; r8++) {
        uint4 su = SP[(size_t)sA[r8] * 32 + q];
        uint4 du = DP[(size_t)dA[r8] * 32 + q];
        float2 s0 = __half22float2(*(__half2*)&su.x), d0 = __half22float2(*(__half2*)&du.x);
        float2 s1 = __half22float2(*(__half2*)&su.y), d1 = __half22float2(*(__half2*)&du.y);
        float2 s2 = __half22float2(*(__half2*)&su.z), d2 = __half22float2(*(__half2*)&du.z);
        float2 s3 = __half22float2(*(__half2*)&su.w), d3 = __half22float2(*(__half2*)&du.w);

        float4 rr;
        rr.x = fmaxf(s0.x + d0.x + b1.x, 0.f);
        rr.y = fmaxf(s1.x + d1.x + b1.y, 0.f);
        rr.z = fmaxf(s2.x + d2.x + b1.z, 0.f);
        rr.w = fmaxf(s3.x + d3.x + b1.w, 0.f);

        float pa = fmaf(fmaxf(s0.y + d0.y + a1.x, 0.f), aw.x,
                   fmaf(fmaxf(s1.y + d1.y + a1.y, 0.f), aw.y,
                   fmaf(fmaxf(s2.y + d2.y + a1.z, 0.f), aw.z,
                        fmaxf(s3.y + d3.y + a1.w, 0.f) * aw.w)));
        #pragma unroll
        for (int off = 16; off > 0; off >>= 1)
            pa += __shfl_xor_sync(0xffffffffu, pa, off);

        float a = 1.f / (1.f + expf(-(pa + ab2)));

        if (e0 + r8 < E) {
            float4 v = make_float4(rr.x * a, rr.y * a, rr.z * a, rr.w * a);
            red_add_v4(&g_z[(size_t)dA[r8] * D + 4*q], v);
            if (lane == 0) atomicAdd(&g_satt[dA[r8]], a);
        }
    }
}

// ---------------- update kernel: 2 GEMMs via tensor cores ----------------
__global__ __launch_bounds__(128, 4)
void upd_kernel(const float* __restrict__ h,
                const float* __restrict__ updB1,
                const float* __restrict__ updB2,
                float* __restrict__ out, int n)
{
    __shared__ __half zsf[TM][136];
    __shared__ __half hid[TM][136];
    int tid = threadIdx.x, lane = tid & 31, w = tid >> 5;
    int g = lane >> 2, t = lane & 3;
    int n0 = blockIdx.x * TM;

    for (int i = tid; i < TM * 32; i += 128) {
        int m = i >> 5, q = i & 31;
        int node = n0 + m; if (node >= n) node = n - 1;
        float4 v = ((const float4*)(g_z + (size_t)node * D))[q];
        *(__half2*)&zsf[m][4*q]     = __floats2half2_rn(v.x, v.y);
        *(__half2*)&zsf[m][4*q + 2] = __floats2half2_rn(v.z, v.w);
    }
    __syncthreads();

    float acc[2][4][4];

    // phase A: hid = relu(z@M + Ht + satt*bb + b1)
    MMA_GEMM(acc, 5, zsf)
    #pragma unroll
    for (int mt = 0; mt < 2; mt++)
    #pragma unroll
    for (int nt = 0; nt < 4; nt++) {
        int row = 16*mt + g, col = 32*w + 8*nt + 2*t;
        float2 bb = *(const float2*)&g_bb[col];
        float2 b1 = *(const float2*)&updB1[col];
        {
            int node = n0 + row;
            int nc = node < n ? node : n - 1;
            float2 ht = *(const float2*)&g_Ht[(size_t)nc * D + col];
            float sa = g_satt[nc];
            float v0 = fmaxf(acc[mt][nt][0] + ht.x + sa * bb.x + b1.x, 0.f);
            float v1 = fmaxf(acc[mt][nt][1] + ht.y + sa * bb.y + b1.y, 0.f);
            *(__half2*)&hid[row][col] = __floats2half2_rn(v0, v1);
        }
        {
            int node = n0 + row + 8;
            int nc = node < n ? node : n - 1;
            float2 ht = *(const float2*)&g_Ht[(size_t)nc * D + col];
            float sa = g_satt[nc];
            float v0 = fmaxf(acc[mt][nt][2] + ht.x + sa * bb.x + b1.x, 0.f);
            float v1 = fmaxf(acc[mt][nt][3] + ht.y + sa * bb.y + b1.y, 0.f);
            *(__half2*)&hid[row + 8][col] = __floats2half2_rn(v0, v1);
        }
    }
    __syncthreads();

    // phase B: out = hid@updW2 + b2 + h + repr
    MMA_GEMM(acc, 6, hid)
    #pragma unroll
    for (int mt = 0; mt < 2; mt++)
    #pragma unroll
    for (int nt = 0; nt < 4; nt++) {
        int row = 16*mt + g, col = 32*w + 8*nt + 2*t;
        float2 b2 = *(const float2*)&updB2[col];
        float2 gr = *(const float2*)&g_repr[col];
        {
            int node = n0 + row;
            if (node < n) {
                float2 hv = *(const float2*)&h[(size_t)node * D + col];
                float2 o = make_float2(acc[mt][nt][0] + b2.x + hv.x + gr.x,
                                       acc[mt][nt][1] + b2.y + hv.y + gr.y);
                *(float2*)&out[(size_t)node * D + col] = o;
            }
        }
        {
            int node = n0 + row + 8;
            if (node < n) {
                float2 hv = *(const float2*)&h[(size_t)node * D + col];
                float2 o = make_float2(acc[mt][nt][2] + b2.x + hv.x + gr.x,
                                       acc[mt][nt][3] + b2.y + hv.y + gr.y);
                *(float2*)&out[(size_t)node * D + col] = o;
            }
        }
    }
}

// ---------------- launch ----------------
extern "C" void kernel_launch(void* const* d_in, const int* in_sizes, int n_in,
                              void* d_out, int out_size)
{
    const float* x  = (const float*)d_in[0];
    const int*   ei = (const int*)d_in[1];     // int32 (JAX x64 disabled)
    const float* msgW1 = (const float*)d_in[2];
    const float* msgB1 = (const float*)d_in[3];
    const float* msgW2 = (const float*)d_in[4];
    const float* msgB2 = (const float*)d_in[5];
    const float* updW1 = (const float*)d_in[6];
    const float* updB1 = (const float*)d_in[7];
    const float* updW2 = (const float*)d_in[8];
    const float* updB2 = (const float*)d_in[9];
    const float* attW1 = (const float*)d_in[10];
    const float* attB1 = (const float*)d_in[11];
    const float* attW2 = (const float*)d_in[12];
    const float* attB2 = (const float*)d_in[13];
    const float* glbW  = (const float*)d_in[14];
    const float* glbB  = (const float*)d_in[15];

    int n = in_sizes[0] / D;
    int E = in_sizes[1] / 2;
    const int* src  = ei;
    const int* dstp = ei + E;
    float* out = (float*)d_out;

    float* h1 = nullptr;  float* zP = nullptr;  float* saP = nullptr;
    cudaGetSymbolAddress((void**)&h1,  g_h1);
    cudaGetSymbolAddress((void**)&zP,  g_z);
    cudaGetSymbolAddress((void**)&saP, g_satt);

    int eb = (E + TM - 1) / TM;
    int nb = (n + TM - 1) / TM;

    // fixed across steps
    mean1_kernel<<<NB_MEAN, 128>>>(x, n);
    repr_kernel<<<1, 128>>>(glbW, glbB, n);
    fuse_kernel<<<D, 128>>>(msgW2, msgB2, updW1);
    wconv_kernel<<<dim3(D, 7), 32>>>(msgW1, attW1, updW1, updW2);

    // step 1: h = x
    cudaMemsetAsync(zP, 0, (size_t)n * D * sizeof(float));
    cudaMemsetAsync(saP, 0, (size_t)n * sizeof(float));
    pre_kernel<<<nb, 128>>>(x, n);
    edge_kernel<<<eb, 128>>>(src, dstp, msgB1, attB1, attW2, attB2, E, n);
    upd_kernel<<<nb, 128>>>(x, updB1, updB2, h1, n);

    // step 2: h = g_h1, output -> d_out
    cudaMemsetAsync(zP, 0, (size_t)n * D * sizeof(float));
    cudaMemsetAsync(saP, 0, (size_t)n * sizeof(float));
    pre_kernel<<<nb, 128>>>(h1, n);
    edge_kernel<<<eb, 128>>>(src, dstp, msgB1, attB1, attW2, attB2, E, n);
    upd_kernel<<<nb, 128>>>(h1, updB1, updB2, out, n);
}